// round 10
// baseline (speedup 1.0000x reference)
#include <cuda_runtime.h>
#include <cuda_bf16.h>
#include <cuda_fp16.h>
#include <cstdint>
#include <math.h>

#define BB 4
#define SS 2048
#define DD 512
#define SCALE_F 0.04419417382415922f  // 1/sqrt(512)

#define BM 128
#define BN 128
#define BK 32
#define PAD 40
#define VPS_SC 4096.0f
#define VPS_DEQ (1.0f / 4096.0f)

// ---------------- scratch ----------------
static __device__ __nv_bfloat16 g_xq[BB * SS * DD];
static __device__ __nv_bfloat16 g_xk[BB * SS * DD];
static __device__ __nv_bfloat16 g_xv[BB * SS * DD];
static __device__ __nv_bfloat16 g_Wq[DD * DD];
static __device__ __nv_bfloat16 g_Wk[DD * DD];
static __device__ __nv_bfloat16 g_Wv[DD * DD];
static __device__ __half        g_qp[BB * SS * DD];
static __device__ __half        g_kp[BB * SS * DD];
static __device__ float         g_vp[BB * SS * DD];
// F: masked (upper) region never written, never read (zero-init device global)
static __device__ __half        g_F[(size_t)BB * SS * SS];
static __device__ __half        g_vpsT[BB * DD * SS];  // (vp/denom)^T * 4096
static __device__ float         g_denom[BB * SS];
static __device__ float         g_colv[BB * DD];

// ---------------- PTX helpers ----------------
__device__ __forceinline__ uint32_t s_u32(const void* p) {
    return (uint32_t)__cvta_generic_to_shared(p);
}
__device__ __forceinline__ void cp16(uint32_t d, const void* s) {
    asm volatile("cp.async.cg.shared.global [%0], [%1], 16;" :: "r"(d), "l"(s));
}
__device__ __forceinline__ void cpcommit() { asm volatile("cp.async.commit_group;"); }
template <int N>
__device__ __forceinline__ void cpwait() {
    asm volatile("cp.async.wait_group %0;" :: "n"(N));
}
__device__ __forceinline__ void ldm4(uint32_t* r, uint32_t a) {
    asm volatile("ldmatrix.sync.aligned.m8n8.x4.shared.b16 {%0,%1,%2,%3}, [%4];"
                 : "=r"(r[0]), "=r"(r[1]), "=r"(r[2]), "=r"(r[3]) : "r"(a));
}
__device__ __forceinline__ void mma16816(float* d, const uint32_t* a, uint32_t b0, uint32_t b1) {
    asm volatile(
        "mma.sync.aligned.m16n8k16.row.col.f32.bf16.bf16.f32 "
        "{%0,%1,%2,%3}, {%4,%5,%6,%7}, {%8,%9}, {%0,%1,%2,%3};"
        : "+f"(d[0]), "+f"(d[1]), "+f"(d[2]), "+f"(d[3])
        : "r"(a[0]), "r"(a[1]), "r"(a[2]), "r"(a[3]), "r"(b0), "r"(b1));
}
__device__ __forceinline__ void mma16816h(uint32_t* d, const uint32_t* a, uint32_t b0, uint32_t b1) {
    asm volatile(
        "mma.sync.aligned.m16n8k16.row.col.f16.f16.f16.f16 "
        "{%0,%1}, {%2,%3,%4,%5}, {%6,%7}, {%0,%1};"
        : "+r"(d[0]), "+r"(d[1])
        : "r"(a[0]), "r"(a[1]), "r"(a[2]), "r"(a[3]), "r"(b0), "r"(b1));
}
__device__ __forceinline__ float expm1_poly(float s) {
    return s * fmaf(s, fmaf(s, fmaf(s, 0.041666667f, 0.16666667f), 0.5f), 1.0f);
}

// ---------------- params ----------------
struct GP {
    const void *A0, *A1, *A2, *B0, *B1, *B2;
    void *C0, *C1, *C2;
    const float *aux0, *aux1, *aux2;
    long long sA, sB, sCb;
    int K, ldc, auxStride;
    float* denom;
};

// ================= proj GEMM: bf16 in, f32 acc (2 CTAs/SM) =================
// z=0,1 -> half out (qp,kp); z=2 -> f32 out (vp)
__global__ __launch_bounds__(256, 2) void gemm_proj(GP p) {
    __shared__ __align__(16) __nv_bfloat16 As[2][BM][PAD];
    __shared__ __align__(16) __nv_bfloat16 Bs[2][BM][PAD];

    const int tid = threadIdx.x;
    const int warp = tid >> 5, lane = tid & 31;
    const int z = blockIdx.z;
    const int m0 = blockIdx.y * BM, n0 = blockIdx.x * BN;

    const __nv_bfloat16* Ag = (const __nv_bfloat16*)(z == 0 ? p.A0 : (z == 1 ? p.A1 : p.A2));
    const __nv_bfloat16* Bg = (const __nv_bfloat16*)(z == 0 ? p.B0 : (z == 1 ? p.B1 : p.B2));
    char* Cg = (char*)(z == 0 ? p.C0 : (z == 1 ? p.C1 : p.C2));
    const float* aux = z == 0 ? p.aux0 : (z == 1 ? p.aux1 : p.aux2);

    const int K = p.K;
    const int KT = K >> 5;
    const int wm = (warp & 3) * 32, wn = (warp >> 2) * 64;
    const int lrow = tid >> 2, lcol = (tid & 3) << 3;

    auto issue = [&](int buf, int kt) {
        const int k0 = kt * BK;
        cp16(s_u32(&As[buf][lrow][lcol]),      Ag + (long long)(m0 + lrow) * K + k0 + lcol);
        cp16(s_u32(&As[buf][lrow + 64][lcol]), Ag + (long long)(m0 + lrow + 64) * K + k0 + lcol);
        cp16(s_u32(&Bs[buf][lrow][lcol]),      Bg + (long long)(n0 + lrow) * K + k0 + lcol);
        cp16(s_u32(&Bs[buf][lrow + 64][lcol]), Bg + (long long)(n0 + lrow + 64) * K + k0 + lcol);
        cpcommit();
    };

    float acc[2][8][4];
#pragma unroll
    for (int i = 0; i < 2; i++)
#pragma unroll
        for (int j = 0; j < 8; j++)
#pragma unroll
            for (int c = 0; c < 4; c++) acc[i][j][c] = 0.f;

    issue(0, 0);

    const int mi = lane >> 3, r8 = lane & 7;
    const int roff = ((mi & 1) << 3) + r8;
    const int koff0 = (mi >> 1) << 3;

    for (int kt = 0; kt < KT; kt++) {
        if (kt + 1 < KT) { issue((kt + 1) & 1, kt + 1); cpwait<1>(); }
        else             { cpwait<0>(); }
        __syncthreads();
        const int buf = kt & 1;
#pragma unroll
        for (int ks = 0; ks < BK; ks += 16) {
            uint32_t af[2][4], bf[4][4];
#pragma unroll
            for (int im = 0; im < 2; im++)
                ldm4(af[im], s_u32(&As[buf][wm + im * 16 + roff][ks + koff0]));
#pragma unroll
            for (int jb = 0; jb < 4; jb++)
                ldm4(bf[jb], s_u32(&Bs[buf][wn + jb * 16 + roff][ks + koff0]));
#pragma unroll
            for (int im = 0; im < 2; im++)
#pragma unroll
                for (int jn = 0; jn < 8; jn++)
                    mma16816(acc[im][jn], af[im], bf[jn >> 1][jn & 1], bf[jn >> 1][2 + (jn & 1)]);
        }
        __syncthreads();
    }

    const int er = lane >> 2, ec = (lane & 3) << 1;
#pragma unroll
    for (int im = 0; im < 2; im++) {
#pragma unroll
        for (int jn = 0; jn < 8; jn++) {
            const int m = m0 + wm + im * 16 + er;
            const int n = n0 + wn + jn * 8 + ec;
            const float ba = aux[n], bb2 = aux[n + 1];
            const float v0 = acc[im][jn][0] + ba, v1 = acc[im][jn][1] + bb2;
            const float v2 = acc[im][jn][2] + ba, v3 = acc[im][jn][3] + bb2;
            if (z == 2) {
                float* Cf = (float*)Cg;
                float2 lo; lo.x = v0; lo.y = v1;
                float2 hi; hi.x = v2; hi.y = v3;
                *(float2*)(Cf + (long long)m * p.ldc + n) = lo;
                *(float2*)(Cf + (long long)(m + 8) * p.ldc + n) = hi;
            } else {
                __half* Ch = (__half*)Cg;
                *(__half2*)(Ch + (long long)m * p.ldc + n) = __floats2half2_rn(v0, v1);
                *(__half2*)(Ch + (long long)(m + 8) * p.ldc + n) = __floats2half2_rn(v2, v3);
            }
        }
    }
}

// ================= f16-acc GEMM (QK, OUT) — 3 CTAs/SM =================
enum { EPI_QK = 0, EPI_OUT = 1 };

template <int EPI>
__global__ __launch_bounds__(256, 3) void gemm_h(GP p) {
    __shared__ __align__(16) __half As[2][BM][PAD];
    __shared__ __align__(16) __half Bs[2][BM][PAD];
    __shared__ float colacc[BN];  // QK only

    const int tid = threadIdx.x;
    const int warp = tid >> 5, lane = tid & 31;

    int m0, n0, z, kend;
    if (EPI == EPI_QK) {
        z = blockIdx.z;
        const int t = blockIdx.x;  // lower-triangle enumeration
        int m_t = (int)floorf((sqrtf(8.0f * (float)t + 1.0f) - 1.0f) * 0.5f);
        while ((m_t + 1) * (m_t + 2) / 2 <= t) m_t++;
        while (m_t * (m_t + 1) / 2 > t) m_t--;
        const int n_t = t - m_t * (m_t + 1) / 2;
        m0 = m_t * BM; n0 = n_t * BN;
        kend = p.K;
        if (tid < BN) colacc[tid] = 0.f;  // ordered before use by mainloop syncs
    } else {
        // longest-K tiles first
        z = blockIdx.z;
        m0 = (gridDim.y - 1 - blockIdx.y) * BM;
        n0 = blockIdx.x * BN;
        kend = m0 + BM;  // F lower-triangular cut
    }

    const __half* Ag = (const __half*)p.A0 + (long long)z * p.sA;
    const __half* Bg = (const __half*)p.B0 + (long long)z * p.sB;
    char* Cg = (char*)p.C0 + (long long)z * p.sCb;
    const float* aux = p.aux0 ? (p.aux0 + (long long)z * p.auxStride) : nullptr;

    const int K = p.K;
    const int KT = kend >> 5;
    const int wm = (warp & 3) * 32, wn = (warp >> 2) * 64;
    const int lrow = tid >> 2, lcol = (tid & 3) << 3;

    auto issue = [&](int buf, int kt) {
        const int k0 = kt * BK;
        cp16(s_u32(&As[buf][lrow][lcol]),      Ag + (long long)(m0 + lrow) * K + k0 + lcol);
        cp16(s_u32(&As[buf][lrow + 64][lcol]), Ag + (long long)(m0 + lrow + 64) * K + k0 + lcol);
        cp16(s_u32(&Bs[buf][lrow][lcol]),      Bg + (long long)(n0 + lrow) * K + k0 + lcol);
        cp16(s_u32(&Bs[buf][lrow + 64][lcol]), Bg + (long long)(n0 + lrow + 64) * K + k0 + lcol);
        cpcommit();
    };

    uint32_t acc[2][8][2];
#pragma unroll
    for (int i = 0; i < 2; i++)
#pragma unroll
        for (int j = 0; j < 8; j++) { acc[i][j][0] = 0u; acc[i][j][1] = 0u; }

    issue(0, 0);

    const int mi = lane >> 3, r8 = lane & 7;
    const int roff = ((mi & 1) << 3) + r8;
    const int koff0 = (mi >> 1) << 3;

    for (int kt = 0; kt < KT; kt++) {
        if (kt + 1 < KT) { issue((kt + 1) & 1, kt + 1); cpwait<1>(); }
        else             { cpwait<0>(); }
        __syncthreads();
        const int buf = kt & 1;
#pragma unroll
        for (int ks = 0; ks < BK; ks += 16) {
            uint32_t af[2][4], bf[4][4];
#pragma unroll
            for (int im = 0; im < 2; im++)
                ldm4(af[im], s_u32(&As[buf][wm + im * 16 + roff][ks + koff0]));
#pragma unroll
            for (int jb = 0; jb < 4; jb++)
                ldm4(bf[jb], s_u32(&Bs[buf][wn + jb * 16 + roff][ks + koff0]));
#pragma unroll
            for (int im = 0; im < 2; im++)
#pragma unroll
                for (int jn = 0; jn < 8; jn++)
                    mma16816h(acc[im][jn], af[im], bf[jn >> 1][jn & 1], bf[jn >> 1][2 + (jn & 1)]);
        }
        __syncthreads();
    }

    const int er = lane >> 2, ec = (lane & 3) << 1;
    float cs0[8], cs1[8];
    if (EPI == EPI_QK) {
#pragma unroll
        for (int j = 0; j < 8; j++) { cs0[j] = 0.f; cs1[j] = 0.f; }
    }
#pragma unroll
    for (int im = 0; im < 2; im++) {
#pragma unroll
        for (int jn = 0; jn < 8; jn++) {
            const int m = m0 + wm + im * 16 + er;
            const int n = n0 + wn + jn * 8 + ec;
            const float2 lo2 = __half22float2(*(__half2*)&acc[im][jn][0]);
            const float2 hi2 = __half22float2(*(__half2*)&acc[im][jn][1]);
            if (EPI == EPI_QK) {
                float v0 = (m     >= n    ) ? expm1_poly(lo2.x * SCALE_F) : 0.f;
                float v1 = (m     >= n + 1) ? expm1_poly(lo2.y * SCALE_F) : 0.f;
                float v2 = (m + 8 >= n    ) ? expm1_poly(hi2.x * SCALE_F) : 0.f;
                float v3 = (m + 8 >= n + 1) ? expm1_poly(hi2.y * SCALE_F) : 0.f;
                cs0[jn] += v0 + v2;
                cs1[jn] += v1 + v3;
                __half* Ch = (__half*)Cg;
                *(__half2*)(Ch + (long long)m * p.ldc + n) = __floats2half2_rn(v0, v1);
                *(__half2*)(Ch + (long long)(m + 8) * p.ldc + n) = __floats2half2_rn(v2, v3);
            } else {
                const float ba = aux[n], bb2 = aux[n + 1];
                float* Cf = (float*)Cg;
                float2 lo; lo.x = lo2.x * VPS_DEQ + ba; lo.y = lo2.y * VPS_DEQ + bb2;
                float2 hi; hi.x = hi2.x * VPS_DEQ + ba; hi.y = hi2.y * VPS_DEQ + bb2;
                *(float2*)(Cf + (long long)m * p.ldc + n) = lo;
                *(float2*)(Cf + (long long)(m + 8) * p.ldc + n) = hi;
            }
        }
    }
    if (EPI == EPI_QK) {
        // fused column sums -> denom (replaces colsum_F pass)
#pragma unroll
        for (int jn = 0; jn < 8; jn++) {
            atomicAdd(&colacc[wn + jn * 8 + ec], cs0[jn]);
            atomicAdd(&colacc[wn + jn * 8 + ec + 1], cs1[jn]);
        }
        __syncthreads();
        if (tid < BN) atomicAdd(&p.denom[z * SS + n0 + tid], colacc[tid]);
    }
}

// ---------------- aux kernels ----------------
struct CvtP { const float4* s[3]; __nv_bfloat162* d[3]; int n4; float *denom, *colv; };
__global__ void cvt_multi(CvtP p) {
    const int t = blockIdx.y;
    const int i = blockIdx.x * 256 + threadIdx.x;
    if (i < p.n4) {
        const float4 x = p.s[t][i];
        p.d[t][2 * i]     = __floats2bfloat162_rn(x.x, x.y);
        p.d[t][2 * i + 1] = __floats2bfloat162_rn(x.z, x.w);
    }
    if (p.denom && t == 0) {  // fused init (small-cvt launch only)
        if (i < BB * SS) p.denom[i] = (float)SS;
        if (i < BB * DD) p.colv[i] = 0.f;
    }
}

// vpsT[b][d][k] = half(vp/denom * 4096)^T ; colv[b][d] += col sums (f32, unscaled)
__global__ void scale_transpose(const float* __restrict__ vp, const float* __restrict__ denom,
                                __half* __restrict__ vpsT, float* __restrict__ colv) {
    __shared__ float t[32][33];
    __shared__ float cp_[32];
    const int b = blockIdx.z;
    const float* vpb = vp + (long long)b * SS * DD;
    __half* vtb = vpsT + (long long)b * DD * SS;
    const int d0 = blockIdx.x * 32, k0 = blockIdx.y * 32;
    const int tx = threadIdx.x, ty = threadIdx.y;
    if (ty == 0) cp_[tx] = 0.f;
    __syncthreads();
    float local = 0.f;
    for (int i = ty; i < 32; i += 8) {
        const int kk = k0 + i;
        const float val = vpb[(long long)kk * DD + d0 + tx] * (1.0f / denom[b * SS + kk]);
        t[i][tx] = val;
        local += val;
    }
    atomicAdd(&cp_[tx], local);
    __syncthreads();
    for (int i = ty; i < 32; i += 8)
        vtb[(long long)(d0 + i) * SS + k0 + tx] = __float2half(t[tx][i] * VPS_SC);
    if (ty == 0) atomicAdd(&colv[b * DD + d0 + tx], cp_[tx]);
}

// ---------------- launch ----------------
extern "C" void kernel_launch(void* const* d_in, const int* in_sizes, int n_in,
                              void* d_out, int out_size) {
    (void)in_sizes; (void)n_in; (void)out_size;
    const float* q   = (const float*)d_in[0];
    const float* k   = (const float*)d_in[1];
    const float* v   = (const float*)d_in[2];
    const float* WQw = (const float*)d_in[3];
    const float* WQb = (const float*)d_in[4];
    const float* WKw = (const float*)d_in[5];
    const float* WKb = (const float*)d_in[6];
    const float* WVw = (const float*)d_in[7];
    const float* WVb = (const float*)d_in[8];

    void *xq, *xk, *xv, *Wq, *Wk, *Wv, *qp, *kp, *vp, *F, *vpsT, *denom, *colv;
    cudaGetSymbolAddress(&xq, g_xq);
    cudaGetSymbolAddress(&xk, g_xk);
    cudaGetSymbolAddress(&xv, g_xv);
    cudaGetSymbolAddress(&Wq, g_Wq);
    cudaGetSymbolAddress(&Wk, g_Wk);
    cudaGetSymbolAddress(&Wv, g_Wv);
    cudaGetSymbolAddress(&qp, g_qp);
    cudaGetSymbolAddress(&kp, g_kp);
    cudaGetSymbolAddress(&vp, g_vp);
    cudaGetSymbolAddress(&F, g_F);
    cudaGetSymbolAddress(&vpsT, g_vpsT);
    cudaGetSymbolAddress(&denom, g_denom);
    cudaGetSymbolAddress(&colv, g_colv);

    const int nx = BB * SS * DD;
    const int nw = DD * DD;

    {
        CvtP pb; pb.s[0] = (const float4*)q; pb.s[1] = (const float4*)k; pb.s[2] = (const float4*)v;
        pb.d[0] = (__nv_bfloat162*)xq; pb.d[1] = (__nv_bfloat162*)xk; pb.d[2] = (__nv_bfloat162*)xv;
        pb.n4 = nx / 4; pb.denom = nullptr; pb.colv = nullptr;
        cvt_multi<<<dim3(nx / 4 / 256, 3), 256>>>(pb);
        CvtP pw; pw.s[0] = (const float4*)WQw; pw.s[1] = (const float4*)WKw; pw.s[2] = (const float4*)WVw;
        pw.d[0] = (__nv_bfloat162*)Wq; pw.d[1] = (__nv_bfloat162*)Wk; pw.d[2] = (__nv_bfloat162*)Wv;
        pw.n4 = nw / 4; pw.denom = (float*)denom; pw.colv = (float*)colv;  // fused init
        cvt_multi<<<dim3(nw / 4 / 256, 3), 256>>>(pw);
    }

    // projections: z=0 qp(half), z=1 kp(half), z=2 vp(f32)
    {
        GP p{};
        p.A0 = xq; p.A1 = xk; p.A2 = xv;
        p.B0 = Wq; p.B1 = Wk; p.B2 = Wv;
        p.C0 = qp; p.C1 = kp; p.C2 = vp;
        p.aux0 = WQb; p.aux1 = WKb; p.aux2 = WVb;
        p.K = DD; p.ldc = DD;
        gemm_proj<<<dim3(DD / BN, BB * SS / BM, 3), 256>>>(p);
    }

    // F[b][q][k] = (q>=k) ? expm1(scale*qk) : 0  (f16 acc), fused colsum -> denom
    {
        GP p{};
        p.A0 = qp; p.B0 = kp; p.C0 = F;
        p.sA = (long long)SS * DD; p.sB = (long long)SS * DD; p.sCb = (long long)SS * SS * 2;
        p.K = DD; p.ldc = SS;
        p.denom = (float*)denom;
        const int NT = SS / BM;
        const int ntri = NT * (NT + 1) / 2;  // 136
        gemm_h<EPI_QK><<<dim3(ntri, 1, BB), 256>>>(p);
    }

    scale_transpose<<<dim3(DD / 32, SS / 32, BB), dim3(32, 8)>>>(
        (const float*)vp, (const float*)denom, (__half*)vpsT, (float*)colv);

    // out = (F . vpsT) * 1/4096 + colv  (f16 acc, K cut at q+BM, longest-first)
    {
        GP p{};
        p.A0 = F; p.B0 = vpsT; p.C0 = d_out;
        p.aux0 = (const float*)colv; p.auxStride = DD;
        p.sA = (long long)SS * SS; p.sB = (long long)DD * SS; p.sCb = (long long)SS * DD * 4;
        p.K = SS; p.ldc = DD;
        gemm_h<EPI_OUT><<<dim3(DD / BN, SS / BM, BB), 256>>>(p);
    }
}

// round 11
// speedup vs baseline: 1.0001x; 1.0001x over previous
#include <cuda_runtime.h>
#include <cuda_bf16.h>
#include <cuda_fp16.h>
#include <cstdint>
#include <math.h>

#define BB 4
#define SS 2048
#define DD 512
#define SCALE_F 0.04419417382415922f  // 1/sqrt(512)

#define BM 128
#define BN 128
#define BK 32
#define PAD 40
#define VPS_SC 4096.0f
#define VPS_DEQ (1.0f / 4096.0f)

// ---------------- scratch ----------------
static __device__ __nv_bfloat16 g_xq[BB * SS * DD];
static __device__ __nv_bfloat16 g_xk[BB * SS * DD];
static __device__ __nv_bfloat16 g_xv[BB * SS * DD];
static __device__ __nv_bfloat16 g_Wq[DD * DD];
static __device__ __nv_bfloat16 g_Wk[DD * DD];
static __device__ __nv_bfloat16 g_Wv[DD * DD];
static __device__ __half        g_qp[BB * SS * DD];
static __device__ __half        g_kp[BB * SS * DD];
static __device__ float         g_vp[BB * SS * DD];
// F: masked (upper) region never written, never read (zero-init device global)
static __device__ __half        g_F[(size_t)BB * SS * SS];
static __device__ __half        g_vpsT[BB * DD * SS];  // (vp/denom)^T * 4096
static __device__ float         g_denom[BB * SS];
static __device__ float         g_colv[BB * DD];

// ---------------- PTX helpers ----------------
__device__ __forceinline__ uint32_t s_u32(const void* p) {
    return (uint32_t)__cvta_generic_to_shared(p);
}
__device__ __forceinline__ void cp16(uint32_t d, const void* s) {
    asm volatile("cp.async.cg.shared.global [%0], [%1], 16;" :: "r"(d), "l"(s));
}
__device__ __forceinline__ void cpcommit() { asm volatile("cp.async.commit_group;"); }
template <int N>
__device__ __forceinline__ void cpwait() {
    asm volatile("cp.async.wait_group %0;" :: "n"(N));
}
__device__ __forceinline__ void ldm4(uint32_t* r, uint32_t a) {
    asm volatile("ldmatrix.sync.aligned.m8n8.x4.shared.b16 {%0,%1,%2,%3}, [%4];"
                 : "=r"(r[0]), "=r"(r[1]), "=r"(r[2]), "=r"(r[3]) : "r"(a));
}
__device__ __forceinline__ void mma16816(float* d, const uint32_t* a, uint32_t b0, uint32_t b1) {
    asm volatile(
        "mma.sync.aligned.m16n8k16.row.col.f32.bf16.bf16.f32 "
        "{%0,%1,%2,%3}, {%4,%5,%6,%7}, {%8,%9}, {%0,%1,%2,%3};"
        : "+f"(d[0]), "+f"(d[1]), "+f"(d[2]), "+f"(d[3])
        : "r"(a[0]), "r"(a[1]), "r"(a[2]), "r"(a[3]), "r"(b0), "r"(b1));
}
__device__ __forceinline__ void mma16816h(uint32_t* d, const uint32_t* a, uint32_t b0, uint32_t b1) {
    asm volatile(
        "mma.sync.aligned.m16n8k16.row.col.f16.f16.f16.f16 "
        "{%0,%1}, {%2,%3,%4,%5}, {%6,%7}, {%0,%1};"
        : "+r"(d[0]), "+r"(d[1])
        : "r"(a[0]), "r"(a[1]), "r"(a[2]), "r"(a[3]), "r"(b0), "r"(b1));
}
__device__ __forceinline__ float expm1_poly(float s) {
    return s * fmaf(s, fmaf(s, fmaf(s, 0.041666667f, 0.16666667f), 0.5f), 1.0f);
}

// ---------------- params ----------------
struct GP {
    const void *A0, *A1, *A2, *B0, *B1, *B2;
    void *C0, *C1, *C2;
    const float *aux0, *aux1, *aux2;
    long long sA, sB, sCb;
    int K, ldc, auxStride;
    float* denom;
};

// ================= proj GEMM: bf16 in, f32 acc (2 CTAs/SM) =================
// z=0,1 -> half out (qp,kp); z=2 -> f32 out (vp)
__global__ __launch_bounds__(256, 2) void gemm_proj(GP p) {
    __shared__ __align__(16) __nv_bfloat16 As[2][BM][PAD];
    __shared__ __align__(16) __nv_bfloat16 Bs[2][BM][PAD];

    const int tid = threadIdx.x;
    const int warp = tid >> 5, lane = tid & 31;
    const int z = blockIdx.z;
    const int m0 = blockIdx.y * BM, n0 = blockIdx.x * BN;

    const __nv_bfloat16* Ag = (const __nv_bfloat16*)(z == 0 ? p.A0 : (z == 1 ? p.A1 : p.A2));
    const __nv_bfloat16* Bg = (const __nv_bfloat16*)(z == 0 ? p.B0 : (z == 1 ? p.B1 : p.B2));
    char* Cg = (char*)(z == 0 ? p.C0 : (z == 1 ? p.C1 : p.C2));
    const float* aux = z == 0 ? p.aux0 : (z == 1 ? p.aux1 : p.aux2);

    const int K = p.K;
    const int KT = K >> 5;
    const int wm = (warp & 3) * 32, wn = (warp >> 2) * 64;
    const int lrow = tid >> 2, lcol = (tid & 3) << 3;

    auto issue = [&](int buf, int kt) {
        const int k0 = kt * BK;
        cp16(s_u32(&As[buf][lrow][lcol]),      Ag + (long long)(m0 + lrow) * K + k0 + lcol);
        cp16(s_u32(&As[buf][lrow + 64][lcol]), Ag + (long long)(m0 + lrow + 64) * K + k0 + lcol);
        cp16(s_u32(&Bs[buf][lrow][lcol]),      Bg + (long long)(n0 + lrow) * K + k0 + lcol);
        cp16(s_u32(&Bs[buf][lrow + 64][lcol]), Bg + (long long)(n0 + lrow + 64) * K + k0 + lcol);
        cpcommit();
    };

    float acc[2][8][4];
#pragma unroll
    for (int i = 0; i < 2; i++)
#pragma unroll
        for (int j = 0; j < 8; j++)
#pragma unroll
            for (int c = 0; c < 4; c++) acc[i][j][c] = 0.f;

    issue(0, 0);

    const int mi = lane >> 3, r8 = lane & 7;
    const int roff = ((mi & 1) << 3) + r8;
    const int koff0 = (mi >> 1) << 3;

    for (int kt = 0; kt < KT; kt++) {
        if (kt + 1 < KT) { issue((kt + 1) & 1, kt + 1); cpwait<1>(); }
        else             { cpwait<0>(); }
        __syncthreads();
        const int buf = kt & 1;
#pragma unroll
        for (int ks = 0; ks < BK; ks += 16) {
            uint32_t af[2][4], bf[4][4];
#pragma unroll
            for (int im = 0; im < 2; im++)
                ldm4(af[im], s_u32(&As[buf][wm + im * 16 + roff][ks + koff0]));
#pragma unroll
            for (int jb = 0; jb < 4; jb++)
                ldm4(bf[jb], s_u32(&Bs[buf][wn + jb * 16 + roff][ks + koff0]));
#pragma unroll
            for (int im = 0; im < 2; im++)
#pragma unroll
                for (int jn = 0; jn < 8; jn++)
                    mma16816(acc[im][jn], af[im], bf[jn >> 1][jn & 1], bf[jn >> 1][2 + (jn & 1)]);
        }
        __syncthreads();
    }

    const int er = lane >> 2, ec = (lane & 3) << 1;
#pragma unroll
    for (int im = 0; im < 2; im++) {
#pragma unroll
        for (int jn = 0; jn < 8; jn++) {
            const int m = m0 + wm + im * 16 + er;
            const int n = n0 + wn + jn * 8 + ec;
            const float ba = aux[n], bb2 = aux[n + 1];
            const float v0 = acc[im][jn][0] + ba, v1 = acc[im][jn][1] + bb2;
            const float v2 = acc[im][jn][2] + ba, v3 = acc[im][jn][3] + bb2;
            if (z == 2) {
                float* Cf = (float*)Cg;
                float2 lo; lo.x = v0; lo.y = v1;
                float2 hi; hi.x = v2; hi.y = v3;
                *(float2*)(Cf + (long long)m * p.ldc + n) = lo;
                *(float2*)(Cf + (long long)(m + 8) * p.ldc + n) = hi;
            } else {
                __half* Ch = (__half*)Cg;
                *(__half2*)(Ch + (long long)m * p.ldc + n) = __floats2half2_rn(v0, v1);
                *(__half2*)(Ch + (long long)(m + 8) * p.ldc + n) = __floats2half2_rn(v2, v3);
            }
        }
    }
}

// ================= f16-acc GEMM (QK: 3 CTAs/SM, OUT: 2 CTAs/SM) =================
enum { EPI_QK = 0, EPI_OUT = 1 };

template <int EPI>
__global__ __launch_bounds__(256, EPI == EPI_QK ? 3 : 2) void gemm_h(GP p) {
    __shared__ __align__(16) __half As[2][BM][PAD];
    __shared__ __align__(16) __half Bs[2][BM][PAD];
    __shared__ float colacc[BN];  // QK only

    const int tid = threadIdx.x;
    const int warp = tid >> 5, lane = tid & 31;

    int m0, n0, z, kend;
    if (EPI == EPI_QK) {
        z = blockIdx.z;
        const int t = blockIdx.x;  // lower-triangle enumeration
        int m_t = (int)floorf((sqrtf(8.0f * (float)t + 1.0f) - 1.0f) * 0.5f);
        while ((m_t + 1) * (m_t + 2) / 2 <= t) m_t++;
        while (m_t * (m_t + 1) / 2 > t) m_t--;
        const int n_t = t - m_t * (m_t + 1) / 2;
        m0 = m_t * BM; n0 = n_t * BN;
        kend = p.K;
        if (tid < BN) colacc[tid] = 0.f;  // ordered before use by mainloop syncs
    } else {
        // longest-K tiles first
        z = blockIdx.z;
        m0 = (gridDim.y - 1 - blockIdx.y) * BM;
        n0 = blockIdx.x * BN;
        kend = m0 + BM;  // F lower-triangular cut
    }

    const __half* Ag = (const __half*)p.A0 + (long long)z * p.sA;
    const __half* Bg = (const __half*)p.B0 + (long long)z * p.sB;
    char* Cg = (char*)p.C0 + (long long)z * p.sCb;
    const float* aux = p.aux0 ? (p.aux0 + (long long)z * p.auxStride) : nullptr;

    const int K = p.K;
    const int KT = kend >> 5;
    const int wm = (warp & 3) * 32, wn = (warp >> 2) * 64;
    const int lrow = tid >> 2, lcol = (tid & 3) << 3;

    auto issue = [&](int buf, int kt) {
        const int k0 = kt * BK;
        cp16(s_u32(&As[buf][lrow][lcol]),      Ag + (long long)(m0 + lrow) * K + k0 + lcol);
        cp16(s_u32(&As[buf][lrow + 64][lcol]), Ag + (long long)(m0 + lrow + 64) * K + k0 + lcol);
        cp16(s_u32(&Bs[buf][lrow][lcol]),      Bg + (long long)(n0 + lrow) * K + k0 + lcol);
        cp16(s_u32(&Bs[buf][lrow + 64][lcol]), Bg + (long long)(n0 + lrow + 64) * K + k0 + lcol);
        cpcommit();
    };

    uint32_t acc[2][8][2];
#pragma unroll
    for (int i = 0; i < 2; i++)
#pragma unroll
        for (int j = 0; j < 8; j++) { acc[i][j][0] = 0u; acc[i][j][1] = 0u; }

    issue(0, 0);

    const int mi = lane >> 3, r8 = lane & 7;
    const int roff = ((mi & 1) << 3) + r8;
    const int koff0 = (mi >> 1) << 3;

    for (int kt = 0; kt < KT; kt++) {
        if (kt + 1 < KT) { issue((kt + 1) & 1, kt + 1); cpwait<1>(); }
        else             { cpwait<0>(); }
        __syncthreads();
        const int buf = kt & 1;
#pragma unroll
        for (int ks = 0; ks < BK; ks += 16) {
            uint32_t af[2][4], bf[4][4];
#pragma unroll
            for (int im = 0; im < 2; im++)
                ldm4(af[im], s_u32(&As[buf][wm + im * 16 + roff][ks + koff0]));
#pragma unroll
            for (int jb = 0; jb < 4; jb++)
                ldm4(bf[jb], s_u32(&Bs[buf][wn + jb * 16 + roff][ks + koff0]));
#pragma unroll
            for (int im = 0; im < 2; im++)
#pragma unroll
                for (int jn = 0; jn < 8; jn++)
                    mma16816h(acc[im][jn], af[im], bf[jn >> 1][jn & 1], bf[jn >> 1][2 + (jn & 1)]);
        }
        __syncthreads();
    }

    const int er = lane >> 2, ec = (lane & 3) << 1;
    float cs0[8], cs1[8];
    if (EPI == EPI_QK) {
#pragma unroll
        for (int j = 0; j < 8; j++) { cs0[j] = 0.f; cs1[j] = 0.f; }
    }
#pragma unroll
    for (int im = 0; im < 2; im++) {
#pragma unroll
        for (int jn = 0; jn < 8; jn++) {
            const int m = m0 + wm + im * 16 + er;
            const int n = n0 + wn + jn * 8 + ec;
            const float2 lo2 = __half22float2(*(__half2*)&acc[im][jn][0]);
            const float2 hi2 = __half22float2(*(__half2*)&acc[im][jn][1]);
            if (EPI == EPI_QK) {
                float v0 = (m     >= n    ) ? expm1_poly(lo2.x * SCALE_F) : 0.f;
                float v1 = (m     >= n + 1) ? expm1_poly(lo2.y * SCALE_F) : 0.f;
                float v2 = (m + 8 >= n    ) ? expm1_poly(hi2.x * SCALE_F) : 0.f;
                float v3 = (m + 8 >= n + 1) ? expm1_poly(hi2.y * SCALE_F) : 0.f;
                cs0[jn] += v0 + v2;
                cs1[jn] += v1 + v3;
                __half* Ch = (__half*)Cg;
                *(__half2*)(Ch + (long long)m * p.ldc + n) = __floats2half2_rn(v0, v1);
                *(__half2*)(Ch + (long long)(m + 8) * p.ldc + n) = __floats2half2_rn(v2, v3);
            } else {
                const float ba = aux[n], bb2 = aux[n + 1];
                float* Cf = (float*)Cg;
                float2 lo; lo.x = lo2.x * VPS_DEQ + ba; lo.y = lo2.y * VPS_DEQ + bb2;
                float2 hi; hi.x = hi2.x * VPS_DEQ + ba; hi.y = hi2.y * VPS_DEQ + bb2;
                *(float2*)(Cf + (long long)m * p.ldc + n) = lo;
                *(float2*)(Cf + (long long)(m + 8) * p.ldc + n) = hi;
            }
        }
    }
    if (EPI == EPI_QK) {
        // fused column sums -> denom (replaces colsum_F pass)
#pragma unroll
        for (int jn = 0; jn < 8; jn++) {
            atomicAdd(&colacc[wn + jn * 8 + ec], cs0[jn]);
            atomicAdd(&colacc[wn + jn * 8 + ec + 1], cs1[jn]);
        }
        __syncthreads();
        if (tid < BN) atomicAdd(&p.denom[z * SS + n0 + tid], colacc[tid]);
    }
}

// ---------------- aux kernels ----------------
struct CvtP { const float4* s[3]; __nv_bfloat162* d[3]; int n4; float *denom, *colv; };
__global__ void cvt_multi(CvtP p) {
    const int t = blockIdx.y;
    const int i = blockIdx.x * 256 + threadIdx.x;
    if (i < p.n4) {
        const float4 x = p.s[t][i];
        p.d[t][2 * i]     = __floats2bfloat162_rn(x.x, x.y);
        p.d[t][2 * i + 1] = __floats2bfloat162_rn(x.z, x.w);
    }
    if (p.denom && t == 0) {  // fused init (small-cvt launch only)
        if (i < BB * SS) p.denom[i] = (float)SS;
        if (i < BB * DD) p.colv[i] = 0.f;
    }
}

// vpsT[b][d][k] = half(vp/denom * 4096)^T ; colv[b][d] += col sums (f32, unscaled)
__global__ void scale_transpose(const float* __restrict__ vp, const float* __restrict__ denom,
                                __half* __restrict__ vpsT, float* __restrict__ colv) {
    __shared__ float t[32][33];
    __shared__ float cp_[32];
    const int b = blockIdx.z;
    const float* vpb = vp + (long long)b * SS * DD;
    __half* vtb = vpsT + (long long)b * DD * SS;
    const int d0 = blockIdx.x * 32, k0 = blockIdx.y * 32;
    const int tx = threadIdx.x, ty = threadIdx.y;
    if (ty == 0) cp_[tx] = 0.f;
    __syncthreads();
    float local = 0.f;
    for (int i = ty; i < 32; i += 8) {
        const int kk = k0 + i;
        const float val = vpb[(long long)kk * DD + d0 + tx] * (1.0f / denom[b * SS + kk]);
        t[i][tx] = val;
        local += val;
    }
    atomicAdd(&cp_[tx], local);
    __syncthreads();
    for (int i = ty; i < 32; i += 8)
        vtb[(long long)(d0 + i) * SS + k0 + tx] = __float2half(t[tx][i] * VPS_SC);
    if (ty == 0) atomicAdd(&colv[b * DD + d0 + tx], cp_[tx]);
}

// ---------------- launch ----------------
extern "C" void kernel_launch(void* const* d_in, const int* in_sizes, int n_in,
                              void* d_out, int out_size) {
    (void)in_sizes; (void)n_in; (void)out_size;
    const float* q   = (const float*)d_in[0];
    const float* k   = (const float*)d_in[1];
    const float* v   = (const float*)d_in[2];
    const float* WQw = (const float*)d_in[3];
    const float* WQb = (const float*)d_in[4];
    const float* WKw = (const float*)d_in[5];
    const float* WKb = (const float*)d_in[6];
    const float* WVw = (const float*)d_in[7];
    const float* WVb = (const float*)d_in[8];

    void *xq, *xk, *xv, *Wq, *Wk, *Wv, *qp, *kp, *vp, *F, *vpsT, *denom, *colv;
    cudaGetSymbolAddress(&xq, g_xq);
    cudaGetSymbolAddress(&xk, g_xk);
    cudaGetSymbolAddress(&xv, g_xv);
    cudaGetSymbolAddress(&Wq, g_Wq);
    cudaGetSymbolAddress(&Wk, g_Wk);
    cudaGetSymbolAddress(&Wv, g_Wv);
    cudaGetSymbolAddress(&qp, g_qp);
    cudaGetSymbolAddress(&kp, g_kp);
    cudaGetSymbolAddress(&vp, g_vp);
    cudaGetSymbolAddress(&F, g_F);
    cudaGetSymbolAddress(&vpsT, g_vpsT);
    cudaGetSymbolAddress(&denom, g_denom);
    cudaGetSymbolAddress(&colv, g_colv);

    const int nx = BB * SS * DD;
    const int nw = DD * DD;

    {
        CvtP pb; pb.s[0] = (const float4*)q; pb.s[1] = (const float4*)k; pb.s[2] = (const float4*)v;
        pb.d[0] = (__nv_bfloat162*)xq; pb.d[1] = (__nv_bfloat162*)xk; pb.d[2] = (__nv_bfloat162*)xv;
        pb.n4 = nx / 4; pb.denom = nullptr; pb.colv = nullptr;
        cvt_multi<<<dim3(nx / 4 / 256, 3), 256>>>(pb);
        CvtP pw; pw.s[0] = (const float4*)WQw; pw.s[1] = (const float4*)WKw; pw.s[2] = (const float4*)WVw;
        pw.d[0] = (__nv_bfloat162*)Wq; pw.d[1] = (__nv_bfloat162*)Wk; pw.d[2] = (__nv_bfloat162*)Wv;
        pw.n4 = nw / 4; pw.denom = (float*)denom; pw.colv = (float*)colv;  // fused init
        cvt_multi<<<dim3(nw / 4 / 256, 3), 256>>>(pw);
    }

    // projections: z=0 qp(half), z=1 kp(half), z=2 vp(f32)
    {
        GP p{};
        p.A0 = xq; p.A1 = xk; p.A2 = xv;
        p.B0 = Wq; p.B1 = Wk; p.B2 = Wv;
        p.C0 = qp; p.C1 = kp; p.C2 = vp;
        p.aux0 = WQb; p.aux1 = WKb; p.aux2 = WVb;
        p.K = DD; p.ldc = DD;
        gemm_proj<<<dim3(DD / BN, BB * SS / BM, 3), 256>>>(p);
    }

    // F[b][q][k] = (q>=k) ? expm1(scale*qk) : 0  (f16 acc, 3 CTAs/SM), fused colsum -> denom
    {
        GP p{};
        p.A0 = qp; p.B0 = kp; p.C0 = F;
        p.sA = (long long)SS * DD; p.sB = (long long)SS * DD; p.sCb = (long long)SS * SS * 2;
        p.K = DD; p.ldc = SS;
        p.denom = (float*)denom;
        const int NT = SS / BM;
        const int ntri = NT * (NT + 1) / 2;  // 136
        gemm_h<EPI_QK><<<dim3(ntri, 1, BB), 256>>>(p);
    }

    scale_transpose<<<dim3(DD / 32, SS / 32, BB), dim3(32, 8)>>>(
        (const float*)vp, (const float*)denom, (__half*)vpsT, (float*)colv);

    // out = (F . vpsT) * 1/4096 + colv  (f16 acc, 2 CTAs/SM, K cut at q+BM, longest-first)
    {
        GP p{};
        p.A0 = F; p.B0 = vpsT; p.C0 = d_out;
        p.aux0 = (const float*)colv; p.auxStride = DD;
        p.sA = (long long)SS * SS; p.sB = (long long)DD * SS; p.sCb = (long long)SS * DD * 4;
        p.K = SS; p.ldc = DD;
        gemm_h<EPI_OUT><<<dim3(DD / BN, SS / BM, BB), 256>>>(p);
    }
}

// round 12
// speedup vs baseline: 1.0340x; 1.0339x over previous
#include <cuda_runtime.h>
#include <cuda_bf16.h>
#include <cuda_fp16.h>
#include <cstdint>
#include <math.h>

#define BB 4
#define SS 2048
#define DD 512
#define SCALE_F 0.04419417382415922f  // 1/sqrt(512)

#define BM 128
#define BN 128
#define BK 32
#define PAD 40
#define VPS_SC 4096.0f
#define VPS_DEQ (1.0f / 4096.0f)

// ---------------- scratch ----------------
static __device__ __nv_bfloat16 g_xq[BB * SS * DD];
static __device__ __nv_bfloat16 g_xk[BB * SS * DD];
static __device__ __nv_bfloat16 g_xv[BB * SS * DD];
static __device__ __nv_bfloat16 g_Wq[DD * DD];
static __device__ __nv_bfloat16 g_Wk[DD * DD];
static __device__ __nv_bfloat16 g_Wv[DD * DD];
static __device__ __half        g_qp[BB * SS * DD];
static __device__ __half        g_kp[BB * SS * DD];
static __device__ float         g_vp[BB * SS * DD];
// F: masked (upper) region never written, never read (zero-init device global)
static __device__ __half        g_F[(size_t)BB * SS * SS];
static __device__ __half        g_vpsT[BB * DD * SS];  // (vp/denom)^T * 4096
static __device__ float         g_denom[BB * SS];
static __device__ float         g_colv[BB * DD];

// ---------------- PTX helpers ----------------
__device__ __forceinline__ uint32_t s_u32(const void* p) {
    return (uint32_t)__cvta_generic_to_shared(p);
}
__device__ __forceinline__ void cp16(uint32_t d, const void* s) {
    asm volatile("cp.async.cg.shared.global [%0], [%1], 16;" :: "r"(d), "l"(s));
}
__device__ __forceinline__ void cpcommit() { asm volatile("cp.async.commit_group;"); }
template <int N>
__device__ __forceinline__ void cpwait() {
    asm volatile("cp.async.wait_group %0;" :: "n"(N));
}
__device__ __forceinline__ void ldm4(uint32_t* r, uint32_t a) {
    asm volatile("ldmatrix.sync.aligned.m8n8.x4.shared.b16 {%0,%1,%2,%3}, [%4];"
                 : "=r"(r[0]), "=r"(r[1]), "=r"(r[2]), "=r"(r[3]) : "r"(a));
}
__device__ __forceinline__ void mma16816(float* d, const uint32_t* a, uint32_t b0, uint32_t b1) {
    asm volatile(
        "mma.sync.aligned.m16n8k16.row.col.f32.bf16.bf16.f32 "
        "{%0,%1,%2,%3}, {%4,%5,%6,%7}, {%8,%9}, {%0,%1,%2,%3};"
        : "+f"(d[0]), "+f"(d[1]), "+f"(d[2]), "+f"(d[3])
        : "r"(a[0]), "r"(a[1]), "r"(a[2]), "r"(a[3]), "r"(b0), "r"(b1));
}
__device__ __forceinline__ void mma16816h(uint32_t* d, const uint32_t* a, uint32_t b0, uint32_t b1) {
    asm volatile(
        "mma.sync.aligned.m16n8k16.row.col.f16.f16.f16.f16 "
        "{%0,%1}, {%2,%3,%4,%5}, {%6,%7}, {%0,%1};"
        : "+r"(d[0]), "+r"(d[1])
        : "r"(a[0]), "r"(a[1]), "r"(a[2]), "r"(a[3]), "r"(b0), "r"(b1));
}
__device__ __forceinline__ float expm1_poly(float s) {
    return s * fmaf(s, fmaf(s, fmaf(s, 0.041666667f, 0.16666667f), 0.5f), 1.0f);
}

// ---------------- params ----------------
struct GP {
    const void *A0, *A1, *A2, *B0, *B1, *B2;
    void *C0, *C1, *C2;
    const float *aux0, *aux1, *aux2;
    long long sA, sB, sCb;
    int K, ldc, auxStride;
    int zbase;
};

// ================= proj GEMM: bf16 in, f32 acc (2 CTAs/SM) =================
// z=0,1 -> half out (qp,kp); z=2 -> f32 out (vp)
__global__ __launch_bounds__(256, 2) void gemm_proj(GP p) {
    __shared__ __align__(16) __nv_bfloat16 As[2][BM][PAD];
    __shared__ __align__(16) __nv_bfloat16 Bs[2][BM][PAD];

    const int tid = threadIdx.x;
    const int warp = tid >> 5, lane = tid & 31;
    const int z = blockIdx.z + p.zbase;
    const int m0 = blockIdx.y * BM, n0 = blockIdx.x * BN;

    const __nv_bfloat16* Ag = (const __nv_bfloat16*)(z == 0 ? p.A0 : (z == 1 ? p.A1 : p.A2));
    const __nv_bfloat16* Bg = (const __nv_bfloat16*)(z == 0 ? p.B0 : (z == 1 ? p.B1 : p.B2));
    char* Cg = (char*)(z == 0 ? p.C0 : (z == 1 ? p.C1 : p.C2));
    const float* aux = z == 0 ? p.aux0 : (z == 1 ? p.aux1 : p.aux2);

    const int K = p.K;
    const int KT = K >> 5;
    const int wm = (warp & 3) * 32, wn = (warp >> 2) * 64;
    const int lrow = tid >> 2, lcol = (tid & 3) << 3;

    auto issue = [&](int buf, int kt) {
        const int k0 = kt * BK;
        cp16(s_u32(&As[buf][lrow][lcol]),      Ag + (long long)(m0 + lrow) * K + k0 + lcol);
        cp16(s_u32(&As[buf][lrow + 64][lcol]), Ag + (long long)(m0 + lrow + 64) * K + k0 + lcol);
        cp16(s_u32(&Bs[buf][lrow][lcol]),      Bg + (long long)(n0 + lrow) * K + k0 + lcol);
        cp16(s_u32(&Bs[buf][lrow + 64][lcol]), Bg + (long long)(n0 + lrow + 64) * K + k0 + lcol);
        cpcommit();
    };

    float acc[2][8][4];
#pragma unroll
    for (int i = 0; i < 2; i++)
#pragma unroll
        for (int j = 0; j < 8; j++)
#pragma unroll
            for (int c = 0; c < 4; c++) acc[i][j][c] = 0.f;

    issue(0, 0);

    const int mi = lane >> 3, r8 = lane & 7;
    const int roff = ((mi & 1) << 3) + r8;
    const int koff0 = (mi >> 1) << 3;

    for (int kt = 0; kt < KT; kt++) {
        if (kt + 1 < KT) { issue((kt + 1) & 1, kt + 1); cpwait<1>(); }
        else             { cpwait<0>(); }
        __syncthreads();
        const int buf = kt & 1;
#pragma unroll
        for (int ks = 0; ks < BK; ks += 16) {
            uint32_t af[2][4], bf[4][4];
#pragma unroll
            for (int im = 0; im < 2; im++)
                ldm4(af[im], s_u32(&As[buf][wm + im * 16 + roff][ks + koff0]));
#pragma unroll
            for (int jb = 0; jb < 4; jb++)
                ldm4(bf[jb], s_u32(&Bs[buf][wn + jb * 16 + roff][ks + koff0]));
#pragma unroll
            for (int im = 0; im < 2; im++)
#pragma unroll
                for (int jn = 0; jn < 8; jn++)
                    mma16816(acc[im][jn], af[im], bf[jn >> 1][jn & 1], bf[jn >> 1][2 + (jn & 1)]);
        }
        __syncthreads();
    }

    const int er = lane >> 2, ec = (lane & 3) << 1;
#pragma unroll
    for (int im = 0; im < 2; im++) {
#pragma unroll
        for (int jn = 0; jn < 8; jn++) {
            const int m = m0 + wm + im * 16 + er;
            const int n = n0 + wn + jn * 8 + ec;
            const float ba = aux[n], bb2 = aux[n + 1];
            const float v0 = acc[im][jn][0] + ba, v1 = acc[im][jn][1] + bb2;
            const float v2 = acc[im][jn][2] + ba, v3 = acc[im][jn][3] + bb2;
            if (z == 2) {
                float* Cf = (float*)Cg;
                float2 lo; lo.x = v0; lo.y = v1;
                float2 hi; hi.x = v2; hi.y = v3;
                *(float2*)(Cf + (long long)m * p.ldc + n) = lo;
                *(float2*)(Cf + (long long)(m + 8) * p.ldc + n) = hi;
            } else {
                __half* Ch = (__half*)Cg;
                *(__half2*)(Ch + (long long)m * p.ldc + n) = __floats2half2_rn(v0, v1);
                *(__half2*)(Ch + (long long)(m + 8) * p.ldc + n) = __floats2half2_rn(v2, v3);
            }
        }
    }
}

// ================= f16-acc GEMM (QK, OUT) — 2 CTAs/SM (R8 config) =================
enum { EPI_QK = 0, EPI_OUT = 1 };

template <int EPI>
__global__ __launch_bounds__(256, 2) void gemm_h(GP p) {
    __shared__ __align__(16) __half As[2][BM][PAD];
    __shared__ __align__(16) __half Bs[2][BM][PAD];

    const int tid = threadIdx.x;
    const int warp = tid >> 5, lane = tid & 31;
    const int z = blockIdx.z;

    int m0, n0;
    if (EPI == EPI_QK) {
        const int t = blockIdx.x;  // lower-triangle enumeration
        int m_t = (int)floorf((sqrtf(8.0f * (float)t + 1.0f) - 1.0f) * 0.5f);
        while ((m_t + 1) * (m_t + 2) / 2 <= t) m_t++;
        while (m_t * (m_t + 1) / 2 > t) m_t--;
        const int n_t = t - m_t * (m_t + 1) / 2;
        m0 = m_t * BM; n0 = n_t * BN;
    } else {
        m0 = (gridDim.y - 1 - blockIdx.y) * BM; n0 = blockIdx.x * BN;  // longest-K first
    }

    const __half* Ag = (const __half*)p.A0 + (long long)z * p.sA;
    const __half* Bg = (const __half*)p.B0 + (long long)z * p.sB;
    char* Cg = (char*)p.C0 + (long long)z * p.sCb;
    const float* aux = p.aux0 ? (p.aux0 + (long long)z * p.auxStride) : nullptr;

    const int K = p.K;
    const int kend = (EPI == EPI_OUT) ? (m0 + BM) : K;
    const int KT = kend >> 5;
    const int wm = (warp & 3) * 32, wn = (warp >> 2) * 64;
    const int lrow = tid >> 2, lcol = (tid & 3) << 3;

    auto issue = [&](int buf, int kt) {
        const int k0 = kt * BK;
        cp16(s_u32(&As[buf][lrow][lcol]),      Ag + (long long)(m0 + lrow) * K + k0 + lcol);
        cp16(s_u32(&As[buf][lrow + 64][lcol]), Ag + (long long)(m0 + lrow + 64) * K + k0 + lcol);
        cp16(s_u32(&Bs[buf][lrow][lcol]),      Bg + (long long)(n0 + lrow) * K + k0 + lcol);
        cp16(s_u32(&Bs[buf][lrow + 64][lcol]), Bg + (long long)(n0 + lrow + 64) * K + k0 + lcol);
        cpcommit();
    };

    uint32_t acc[2][8][2];
#pragma unroll
    for (int i = 0; i < 2; i++)
#pragma unroll
        for (int j = 0; j < 8; j++) { acc[i][j][0] = 0u; acc[i][j][1] = 0u; }

    issue(0, 0);

    const int mi = lane >> 3, r8 = lane & 7;
    const int roff = ((mi & 1) << 3) + r8;
    const int koff0 = (mi >> 1) << 3;

    for (int kt = 0; kt < KT; kt++) {
        if (kt + 1 < KT) { issue((kt + 1) & 1, kt + 1); cpwait<1>(); }
        else             { cpwait<0>(); }
        __syncthreads();
        const int buf = kt & 1;
#pragma unroll
        for (int ks = 0; ks < BK; ks += 16) {
            uint32_t af[2][4], bf[4][4];
#pragma unroll
            for (int im = 0; im < 2; im++)
                ldm4(af[im], s_u32(&As[buf][wm + im * 16 + roff][ks + koff0]));
#pragma unroll
            for (int jb = 0; jb < 4; jb++)
                ldm4(bf[jb], s_u32(&Bs[buf][wn + jb * 16 + roff][ks + koff0]));
#pragma unroll
            for (int im = 0; im < 2; im++)
#pragma unroll
                for (int jn = 0; jn < 8; jn++)
                    mma16816h(acc[im][jn], af[im], bf[jn >> 1][jn & 1], bf[jn >> 1][2 + (jn & 1)]);
        }
        __syncthreads();
    }

    const int er = lane >> 2, ec = (lane & 3) << 1;
#pragma unroll
    for (int im = 0; im < 2; im++) {
#pragma unroll
        for (int jn = 0; jn < 8; jn++) {
            const int m = m0 + wm + im * 16 + er;
            const int n = n0 + wn + jn * 8 + ec;
            const float2 lo2 = __half22float2(*(__half2*)&acc[im][jn][0]);
            const float2 hi2 = __half22float2(*(__half2*)&acc[im][jn][1]);
            if (EPI == EPI_QK) {
                float v0 = (m     >= n    ) ? expm1_poly(lo2.x * SCALE_F) : 0.f;
                float v1 = (m     >= n + 1) ? expm1_poly(lo2.y * SCALE_F) : 0.f;
                float v2 = (m + 8 >= n    ) ? expm1_poly(hi2.x * SCALE_F) : 0.f;
                float v3 = (m + 8 >= n + 1) ? expm1_poly(hi2.y * SCALE_F) : 0.f;
                __half* Ch = (__half*)Cg;
                *(__half2*)(Ch + (long long)m * p.ldc + n) = __floats2half2_rn(v0, v1);
                *(__half2*)(Ch + (long long)(m + 8) * p.ldc + n) = __floats2half2_rn(v2, v3);
            } else {
                const float ba = aux[n], bb2 = aux[n + 1];
                float* Cf = (float*)Cg;
                float2 lo; lo.x = lo2.x * VPS_DEQ + ba; lo.y = lo2.y * VPS_DEQ + bb2;
                float2 hi; hi.x = hi2.x * VPS_DEQ + ba; hi.y = hi2.y * VPS_DEQ + bb2;
                *(float2*)(Cf + (long long)m * p.ldc + n) = lo;
                *(float2*)(Cf + (long long)(m + 8) * p.ldc + n) = hi;
            }
        }
    }
}

// ---------------- aux kernels ----------------
struct CvtP { const float4* s[3]; __nv_bfloat162* d[3]; int n4; };
__global__ void cvt_multi(CvtP p) {
    const int t = blockIdx.y;
    const int i = blockIdx.x * 256 + threadIdx.x;
    if (i < p.n4) {
        const float4 x = p.s[t][i];
        p.d[t][2 * i]     = __floats2bfloat162_rn(x.x, x.y);
        p.d[t][2 * i + 1] = __floats2bfloat162_rn(x.z, x.w);
    }
}

__global__ void init_dc(float* __restrict__ denom, float* __restrict__ colv) {
    const int i = blockIdx.x * blockDim.x + threadIdx.x;
    if (i < BB * SS) denom[i] = (float)SS;
    if (i < BB * DD) colv[i] = 0.f;
}

// denom[b][n] += sum_{m>=n} F[b][m][n]
__global__ void colsum_F(const __half* __restrict__ F, float* __restrict__ denom) {
    const int b = blockIdx.z;
    const int n = blockIdx.x * 128 + threadIdx.x;
    const int m0 = blockIdx.y * 256;
    const int mstart = max(m0, n), mend = m0 + 256;
    if (mstart >= mend) return;
    const __half* Fb = F + (long long)b * SS * SS;
    float s = 0.f;
    for (int m = mstart; m < mend; m++) s += __half2float(Fb[(long long)m * SS + n]);
    atomicAdd(&denom[b * SS + n], s);
}

// vpsT[b][d][k] = half(vp/denom * 4096)^T ; colv[b][d] += col sums (f32, unscaled)
__global__ void scale_transpose(const float* __restrict__ vp, const float* __restrict__ denom,
                                __half* __restrict__ vpsT, float* __restrict__ colv) {
    __shared__ float t[32][33];
    __shared__ float cp_[32];
    const int b = blockIdx.z;
    const float* vpb = vp + (long long)b * SS * DD;
    __half* vtb = vpsT + (long long)b * DD * SS;
    const int d0 = blockIdx.x * 32, k0 = blockIdx.y * 32;
    const int tx = threadIdx.x, ty = threadIdx.y;
    if (ty == 0) cp_[tx] = 0.f;
    __syncthreads();
    float local = 0.f;
    for (int i = ty; i < 32; i += 8) {
        const int kk = k0 + i;
        const float val = vpb[(long long)kk * DD + d0 + tx] * (1.0f / denom[b * SS + kk]);
        t[i][tx] = val;
        local += val;
    }
    atomicAdd(&cp_[tx], local);
    __syncthreads();
    for (int i = ty; i < 32; i += 8)
        vtb[(long long)(d0 + i) * SS + k0 + tx] = __float2half(t[tx][i] * VPS_SC);
    if (ty == 0) atomicAdd(&colv[b * DD + d0 + tx], cp_[tx]);
}

// ---------------- launch ----------------
extern "C" void kernel_launch(void* const* d_in, const int* in_sizes, int n_in,
                              void* d_out, int out_size) {
    (void)in_sizes; (void)n_in; (void)out_size;
    const float* q   = (const float*)d_in[0];
    const float* k   = (const float*)d_in[1];
    const float* v   = (const float*)d_in[2];
    const float* WQw = (const float*)d_in[3];
    const float* WQb = (const float*)d_in[4];
    const float* WKw = (const float*)d_in[5];
    const float* WKb = (const float*)d_in[6];
    const float* WVw = (const float*)d_in[7];
    const float* WVb = (const float*)d_in[8];

    void *xq, *xk, *xv, *Wq, *Wk, *Wv, *qp, *kp, *vp, *F, *vpsT, *denom, *colv;
    cudaGetSymbolAddress(&xq, g_xq);
    cudaGetSymbolAddress(&xk, g_xk);
    cudaGetSymbolAddress(&xv, g_xv);
    cudaGetSymbolAddress(&Wq, g_Wq);
    cudaGetSymbolAddress(&Wk, g_Wk);
    cudaGetSymbolAddress(&Wv, g_Wv);
    cudaGetSymbolAddress(&qp, g_qp);
    cudaGetSymbolAddress(&kp, g_kp);
    cudaGetSymbolAddress(&vp, g_vp);
    cudaGetSymbolAddress(&F, g_F);
    cudaGetSymbolAddress(&vpsT, g_vpsT);
    cudaGetSymbolAddress(&denom, g_denom);
    cudaGetSymbolAddress(&colv, g_colv);

    // one-time stream/event infra (no device memory; created outside graph capture
    // on the first (correctness) call, reused identically on every call)
    static cudaStream_t sB = nullptr;
    static cudaEvent_t evX = nullptr, evV = nullptr;
    if (!sB) {
        cudaStreamCreateWithFlags(&sB, cudaStreamNonBlocking);
        cudaEventCreateWithFlags(&evX, cudaEventDisableTiming);
        cudaEventCreateWithFlags(&evV, cudaEventDisableTiming);
    }

    const int nx = BB * SS * DD;
    const int nw = DD * DD;

    // stream 0: cvts + init
    {
        CvtP pb; pb.s[0] = (const float4*)q; pb.s[1] = (const float4*)k; pb.s[2] = (const float4*)v;
        pb.d[0] = (__nv_bfloat162*)xq; pb.d[1] = (__nv_bfloat162*)xk; pb.d[2] = (__nv_bfloat162*)xv;
        pb.n4 = nx / 4;
        cvt_multi<<<dim3(nx / 4 / 256, 3), 256>>>(pb);
        CvtP pw; pw.s[0] = (const float4*)WQw; pw.s[1] = (const float4*)WKw; pw.s[2] = (const float4*)WVw;
        pw.d[0] = (__nv_bfloat162*)Wq; pw.d[1] = (__nv_bfloat162*)Wk; pw.d[2] = (__nv_bfloat162*)Wv;
        pw.n4 = nw / 4;
        cvt_multi<<<dim3(nw / 4 / 256, 3), 256>>>(pw);
    }
    init_dc<<<(BB * SS + 255) / 256, 256>>>((float*)denom, (float*)colv);
    cudaEventRecord(evX, 0);

    // stream B: vp projection (z=2), concurrent with proj-qk + QK on stream 0
    {
        cudaStreamWaitEvent(sB, evX, 0);
        GP p{};
        p.A0 = xq; p.A1 = xk; p.A2 = xv;
        p.B0 = Wq; p.B1 = Wk; p.B2 = Wv;
        p.C0 = qp; p.C1 = kp; p.C2 = vp;
        p.aux0 = WQb; p.aux1 = WKb; p.aux2 = WVb;
        p.K = DD; p.ldc = DD; p.zbase = 2;
        gemm_proj<<<dim3(DD / BN, BB * SS / BM, 1), 256, 0, sB>>>(p);
        cudaEventRecord(evV, sB);
    }

    // stream 0: qp/kp projections (z=0,1)
    {
        GP p{};
        p.A0 = xq; p.A1 = xk; p.A2 = xv;
        p.B0 = Wq; p.B1 = Wk; p.B2 = Wv;
        p.C0 = qp; p.C1 = kp; p.C2 = vp;
        p.aux0 = WQb; p.aux1 = WKb; p.aux2 = WVb;
        p.K = DD; p.ldc = DD; p.zbase = 0;
        gemm_proj<<<dim3(DD / BN, BB * SS / BM, 2), 256>>>(p);
    }

    // F[b][q][k] = (q>=k) ? expm1(scale*qk) : 0  (f16 acc) — triangle tiles
    {
        GP p{};
        p.A0 = qp; p.B0 = kp; p.C0 = F;
        p.sA = (long long)SS * DD; p.sB = (long long)SS * DD; p.sCb = (long long)SS * SS * 2;
        p.K = DD; p.ldc = SS;
        const int NT = SS / BM;
        const int ntri = NT * (NT + 1) / 2;  // 136
        gemm_h<EPI_QK><<<dim3(ntri, 1, BB), 256>>>(p);
    }

    colsum_F<<<dim3(SS / 128, 8, BB), 128>>>((const __half*)F, (float*)denom);

    // join: scale_transpose needs vp (stream B) + denom (stream 0)
    cudaStreamWaitEvent(0, evV, 0);
    scale_transpose<<<dim3(DD / 32, SS / 32, BB), dim3(32, 8)>>>(
        (const float*)vp, (const float*)denom, (__half*)vpsT, (float*)colv);

    // out = (F . vpsT) * 1/4096 + colv  (f16 acc, K cut at q+BM, longest-first)
    {
        GP p{};
        p.A0 = F; p.B0 = vpsT; p.C0 = d_out;
        p.aux0 = (const float*)colv; p.auxStride = DD;
        p.sA = (long long)SS * SS; p.sB = (long long)DD * SS; p.sCb = (long long)SS * DD * 4;
        p.K = SS; p.ldc = DD;
        gemm_h<EPI_OUT><<<dim3(DD / BN, SS / BM, BB), 256>>>(p);
    }
}

// round 13
// speedup vs baseline: 1.0980x; 1.0618x over previous
#include <cuda_runtime.h>
#include <cuda_bf16.h>
#include <cuda_fp16.h>
#include <cstdint>
#include <math.h>

#define BB 4
#define SS 2048
#define DD 512
#define SCALE_F 0.04419417382415922f  // 1/sqrt(512)

#define BM 128
#define BN 128
#define BK 32
#define PAD 40
#define VPS_SC 4096.0f
#define VPS_DEQ (1.0f / 4096.0f)

// ---------------- scratch ----------------
static __device__ __nv_bfloat16 g_xq[BB * SS * DD];
static __device__ __nv_bfloat16 g_xk[BB * SS * DD];
static __device__ __nv_bfloat16 g_xv[BB * SS * DD];
static __device__ __nv_bfloat16 g_Wq[DD * DD];
static __device__ __nv_bfloat16 g_Wk[DD * DD];
static __device__ __nv_bfloat16 g_Wv[DD * DD];
static __device__ __half        g_qp[BB * SS * DD];
static __device__ __half        g_kp[BB * SS * DD];
static __device__ float         g_vp[BB * SS * DD];
// F: masked (upper) region never written, never read (zero-init device global)
static __device__ __half        g_F[(size_t)BB * SS * SS];
static __device__ __half        g_vpsT[BB * DD * SS];  // (vp/denom)^T * 4096
static __device__ float         g_denom[BB * SS];
static __device__ float         g_colv[BB * DD];

// ---------------- PTX helpers ----------------
__device__ __forceinline__ uint32_t s_u32(const void* p) {
    return (uint32_t)__cvta_generic_to_shared(p);
}
__device__ __forceinline__ void cp16(uint32_t d, const void* s) {
    asm volatile("cp.async.cg.shared.global [%0], [%1], 16;" :: "r"(d), "l"(s));
}
__device__ __forceinline__ void cpcommit() { asm volatile("cp.async.commit_group;"); }
template <int N>
__device__ __forceinline__ void cpwait() {
    asm volatile("cp.async.wait_group %0;" :: "n"(N));
}
__device__ __forceinline__ void ldm4(uint32_t* r, uint32_t a) {
    asm volatile("ldmatrix.sync.aligned.m8n8.x4.shared.b16 {%0,%1,%2,%3}, [%4];"
                 : "=r"(r[0]), "=r"(r[1]), "=r"(r[2]), "=r"(r[3]) : "r"(a));
}
__device__ __forceinline__ void mma16816(float* d, const uint32_t* a, uint32_t b0, uint32_t b1) {
    asm volatile(
        "mma.sync.aligned.m16n8k16.row.col.f32.bf16.bf16.f32 "
        "{%0,%1,%2,%3}, {%4,%5,%6,%7}, {%8,%9}, {%0,%1,%2,%3};"
        : "+f"(d[0]), "+f"(d[1]), "+f"(d[2]), "+f"(d[3])
        : "r"(a[0]), "r"(a[1]), "r"(a[2]), "r"(a[3]), "r"(b0), "r"(b1));
}
__device__ __forceinline__ void mma16816h(uint32_t* d, const uint32_t* a, uint32_t b0, uint32_t b1) {
    asm volatile(
        "mma.sync.aligned.m16n8k16.row.col.f16.f16.f16.f16 "
        "{%0,%1}, {%2,%3,%4,%5}, {%6,%7}, {%0,%1};"
        : "+r"(d[0]), "+r"(d[1])
        : "r"(a[0]), "r"(a[1]), "r"(a[2]), "r"(a[3]), "r"(b0), "r"(b1));
}
__device__ __forceinline__ float expm1_poly(float s) {
    return s * fmaf(s, fmaf(s, fmaf(s, 0.041666667f, 0.16666667f), 0.5f), 1.0f);
}

// ---------------- params ----------------
struct GP {
    const void *A0, *A1, *A2, *B0, *B1, *B2;
    void *C0, *C1, *C2;
    const float *aux0, *aux1, *aux2;
    long long sA, sB, sCb;
    int K, ldc, auxStride;
    int zbase;
};

// ================= proj GEMM: bf16 in, f32 acc (2 CTAs/SM) =================
// z=0,1 -> half out (qp,kp); z=2 -> f32 out (vp)
__global__ __launch_bounds__(256, 2) void gemm_proj(GP p) {
    __shared__ __align__(16) __nv_bfloat16 As[2][BM][PAD];
    __shared__ __align__(16) __nv_bfloat16 Bs[2][BM][PAD];

    const int tid = threadIdx.x;
    const int warp = tid >> 5, lane = tid & 31;
    const int z = blockIdx.z + p.zbase;
    const int m0 = blockIdx.y * BM, n0 = blockIdx.x * BN;

    const __nv_bfloat16* Ag = (const __nv_bfloat16*)(z == 0 ? p.A0 : (z == 1 ? p.A1 : p.A2));
    const __nv_bfloat16* Bg = (const __nv_bfloat16*)(z == 0 ? p.B0 : (z == 1 ? p.B1 : p.B2));
    char* Cg = (char*)(z == 0 ? p.C0 : (z == 1 ? p.C1 : p.C2));
    const float* aux = z == 0 ? p.aux0 : (z == 1 ? p.aux1 : p.aux2);

    const int K = p.K;
    const int KT = K >> 5;
    const int wm = (warp & 3) * 32, wn = (warp >> 2) * 64;
    const int lrow = tid >> 2, lcol = (tid & 3) << 3;

    auto issue = [&](int buf, int kt) {
        const int k0 = kt * BK;
        cp16(s_u32(&As[buf][lrow][lcol]),      Ag + (long long)(m0 + lrow) * K + k0 + lcol);
        cp16(s_u32(&As[buf][lrow + 64][lcol]), Ag + (long long)(m0 + lrow + 64) * K + k0 + lcol);
        cp16(s_u32(&Bs[buf][lrow][lcol]),      Bg + (long long)(n0 + lrow) * K + k0 + lcol);
        cp16(s_u32(&Bs[buf][lrow + 64][lcol]), Bg + (long long)(n0 + lrow + 64) * K + k0 + lcol);
        cpcommit();
    };

    float acc[2][8][4];
#pragma unroll
    for (int i = 0; i < 2; i++)
#pragma unroll
        for (int j = 0; j < 8; j++)
#pragma unroll
            for (int c = 0; c < 4; c++) acc[i][j][c] = 0.f;

    issue(0, 0);

    const int mi = lane >> 3, r8 = lane & 7;
    const int roff = ((mi & 1) << 3) + r8;
    const int koff0 = (mi >> 1) << 3;

    for (int kt = 0; kt < KT; kt++) {
        if (kt + 1 < KT) { issue((kt + 1) & 1, kt + 1); cpwait<1>(); }
        else             { cpwait<0>(); }
        __syncthreads();
        const int buf = kt & 1;
#pragma unroll
        for (int ks = 0; ks < BK; ks += 16) {
            uint32_t af[2][4], bf[4][4];
#pragma unroll
            for (int im = 0; im < 2; im++)
                ldm4(af[im], s_u32(&As[buf][wm + im * 16 + roff][ks + koff0]));
#pragma unroll
            for (int jb = 0; jb < 4; jb++)
                ldm4(bf[jb], s_u32(&Bs[buf][wn + jb * 16 + roff][ks + koff0]));
#pragma unroll
            for (int im = 0; im < 2; im++)
#pragma unroll
                for (int jn = 0; jn < 8; jn++)
                    mma16816(acc[im][jn], af[im], bf[jn >> 1][jn & 1], bf[jn >> 1][2 + (jn & 1)]);
        }
        __syncthreads();
    }

    const int er = lane >> 2, ec = (lane & 3) << 1;
#pragma unroll
    for (int im = 0; im < 2; im++) {
#pragma unroll
        for (int jn = 0; jn < 8; jn++) {
            const int m = m0 + wm + im * 16 + er;
            const int n = n0 + wn + jn * 8 + ec;
            const float ba = aux[n], bb2 = aux[n + 1];
            const float v0 = acc[im][jn][0] + ba, v1 = acc[im][jn][1] + bb2;
            const float v2 = acc[im][jn][2] + ba, v3 = acc[im][jn][3] + bb2;
            if (z == 2) {
                float* Cf = (float*)Cg;
                float2 lo; lo.x = v0; lo.y = v1;
                float2 hi; hi.x = v2; hi.y = v3;
                *(float2*)(Cf + (long long)m * p.ldc + n) = lo;
                *(float2*)(Cf + (long long)(m + 8) * p.ldc + n) = hi;
            } else {
                __half* Ch = (__half*)Cg;
                *(__half2*)(Ch + (long long)m * p.ldc + n) = __floats2half2_rn(v0, v1);
                *(__half2*)(Ch + (long long)(m + 8) * p.ldc + n) = __floats2half2_rn(v2, v3);
            }
        }
    }
}

// ================= f16-acc GEMM (QK, OUT) — 2 CTAs/SM =================
enum { EPI_QK = 0, EPI_OUT = 1 };

template <int EPI>
__global__ __launch_bounds__(256, 2) void gemm_h(GP p) {
    __shared__ __align__(16) __half As[2][BM][PAD];
    __shared__ __align__(16) __half Bs[2][BM][PAD];

    const int tid = threadIdx.x;
    const int warp = tid >> 5, lane = tid & 31;

    int m0, n0, z, kbeg, kfin, lev = 0;
    if (EPI == EPI_QK) {
        z = blockIdx.z;
        const int t = blockIdx.x;  // lower-triangle enumeration
        int m_t = (int)floorf((sqrtf(8.0f * (float)t + 1.0f) - 1.0f) * 0.5f);
        while ((m_t + 1) * (m_t + 2) / 2 <= t) m_t++;
        while (m_t * (m_t + 1) / 2 > t) m_t--;
        const int n_t = t - m_t * (m_t + 1) / 2;
        m0 = m_t * BM; n0 = n_t * BN;
        kbeg = 0; kfin = p.K;
    } else {
        // split-K schedule: 24 groups of 16 CTAs, ordered by chunk K desc.
        // levels 9..16 split at lev*64 (BK multiple); levels 1..8 unsplit.
        static const signed char LEVT[24] = {16,16, 8,15,15,14,14, 7,13,13,12,12,
                                              6,11,11,10,10, 5, 9, 9, 4, 3, 2, 1};
        static const signed char CHT[24]  = { 0, 1,-1, 0, 1, 0, 1,-1, 0, 1, 0, 1,
                                             -1, 0, 1, 0, 1,-1, 0, 1,-1,-1,-1,-1};
        const int g = blockIdx.x >> 4, idx = blockIdx.x & 15;
        lev = LEVT[g];
        const int ch = CHT[g];
        m0 = (lev - 1) * BM;
        z = idx >> 2;
        n0 = (idx & 3) * BN;
        if (ch < 0) { kbeg = 0; kfin = lev * BM; }
        else {
            const int half = lev * 64;  // multiple of 32
            kbeg = ch ? half : 0;
            kfin = ch ? lev * BM : half;
        }
    }

    const __half* Ag = (const __half*)p.A0 + (long long)z * p.sA;
    const __half* Bg = (const __half*)p.B0 + (long long)z * p.sB;
    char* Cg = (char*)p.C0 + (long long)z * p.sCb;
    const float* aux = p.aux0 ? (p.aux0 + (long long)z * p.auxStride) : nullptr;

    const int K = p.K;
    const int KTb = kbeg >> 5, KTe = kfin >> 5;
    const int wm = (warp & 3) * 32, wn = (warp >> 2) * 64;
    const int lrow = tid >> 2, lcol = (tid & 3) << 3;

    auto issue = [&](int buf, int kt) {
        const int k0 = kt * BK;
        cp16(s_u32(&As[buf][lrow][lcol]),      Ag + (long long)(m0 + lrow) * K + k0 + lcol);
        cp16(s_u32(&As[buf][lrow + 64][lcol]), Ag + (long long)(m0 + lrow + 64) * K + k0 + lcol);
        cp16(s_u32(&Bs[buf][lrow][lcol]),      Bg + (long long)(n0 + lrow) * K + k0 + lcol);
        cp16(s_u32(&Bs[buf][lrow + 64][lcol]), Bg + (long long)(n0 + lrow + 64) * K + k0 + lcol);
        cpcommit();
    };

    uint32_t acc[2][8][2];
#pragma unroll
    for (int i = 0; i < 2; i++)
#pragma unroll
        for (int j = 0; j < 8; j++) { acc[i][j][0] = 0u; acc[i][j][1] = 0u; }

    issue(KTb & 1, KTb);

    const int mi = lane >> 3, r8 = lane & 7;
    const int roff = ((mi & 1) << 3) + r8;
    const int koff0 = (mi >> 1) << 3;

    for (int kt = KTb; kt < KTe; kt++) {
        if (kt + 1 < KTe) { issue((kt + 1) & 1, kt + 1); cpwait<1>(); }
        else              { cpwait<0>(); }
        __syncthreads();
        const int buf = kt & 1;
#pragma unroll
        for (int ks = 0; ks < BK; ks += 16) {
            uint32_t af[2][4], bf[4][4];
#pragma unroll
            for (int im = 0; im < 2; im++)
                ldm4(af[im], s_u32(&As[buf][wm + im * 16 + roff][ks + koff0]));
#pragma unroll
            for (int jb = 0; jb < 4; jb++)
                ldm4(bf[jb], s_u32(&Bs[buf][wn + jb * 16 + roff][ks + koff0]));
#pragma unroll
            for (int im = 0; im < 2; im++)
#pragma unroll
                for (int jn = 0; jn < 8; jn++)
                    mma16816h(acc[im][jn], af[im], bf[jn >> 1][jn & 1], bf[jn >> 1][2 + (jn & 1)]);
        }
        __syncthreads();
    }

    const int er = lane >> 2, ec = (lane & 3) << 1;
#pragma unroll
    for (int im = 0; im < 2; im++) {
#pragma unroll
        for (int jn = 0; jn < 8; jn++) {
            const int m = m0 + wm + im * 16 + er;
            const int n = n0 + wn + jn * 8 + ec;
            const float2 lo2 = __half22float2(*(__half2*)&acc[im][jn][0]);
            const float2 hi2 = __half22float2(*(__half2*)&acc[im][jn][1]);
            if (EPI == EPI_QK) {
                float v0 = (m     >= n    ) ? expm1_poly(lo2.x * SCALE_F) : 0.f;
                float v1 = (m     >= n + 1) ? expm1_poly(lo2.y * SCALE_F) : 0.f;
                float v2 = (m + 8 >= n    ) ? expm1_poly(hi2.x * SCALE_F) : 0.f;
                float v3 = (m + 8 >= n + 1) ? expm1_poly(hi2.y * SCALE_F) : 0.f;
                __half* Ch = (__half*)Cg;
                *(__half2*)(Ch + (long long)m * p.ldc + n) = __floats2half2_rn(v0, v1);
                *(__half2*)(Ch + (long long)(m + 8) * p.ldc + n) = __floats2half2_rn(v2, v3);
            } else {
                float* Cf = (float*)Cg;
                if (lev >= 9) {
                    // rows >= 1024 pre-initialized with colv; RED-accumulate
                    atomicAdd(Cf + (long long)m * p.ldc + n,           lo2.x * VPS_DEQ);
                    atomicAdd(Cf + (long long)m * p.ldc + n + 1,       lo2.y * VPS_DEQ);
                    atomicAdd(Cf + (long long)(m + 8) * p.ldc + n,     hi2.x * VPS_DEQ);
                    atomicAdd(Cf + (long long)(m + 8) * p.ldc + n + 1, hi2.y * VPS_DEQ);
                } else {
                    const float ba = aux[n], bb2 = aux[n + 1];
                    float2 lo; lo.x = lo2.x * VPS_DEQ + ba; lo.y = lo2.y * VPS_DEQ + bb2;
                    float2 hi; hi.x = hi2.x * VPS_DEQ + ba; hi.y = hi2.y * VPS_DEQ + bb2;
                    *(float2*)(Cf + (long long)m * p.ldc + n) = lo;
                    *(float2*)(Cf + (long long)(m + 8) * p.ldc + n) = hi;
                }
            }
        }
    }
}

// ---------------- aux kernels ----------------
struct CvtP { const float4* s[3]; __nv_bfloat162* d[3]; int n4; };
__global__ void cvt_multi(CvtP p) {
    const int t = blockIdx.y;
    const int i = blockIdx.x * 256 + threadIdx.x;
    if (i < p.n4) {
        const float4 x = p.s[t][i];
        p.d[t][2 * i]     = __floats2bfloat162_rn(x.x, x.y);
        p.d[t][2 * i + 1] = __floats2bfloat162_rn(x.z, x.w);
    }
}

__global__ void init_dc(float* __restrict__ denom, float* __restrict__ colv) {
    const int i = blockIdx.x * blockDim.x + threadIdx.x;
    if (i < BB * SS) denom[i] = (float)SS;
    if (i < BB * DD) colv[i] = 0.f;
}

// denom[b][n] += sum_{m>=n} F[b][m][n]
__global__ void colsum_F(const __half* __restrict__ F, float* __restrict__ denom) {
    const int b = blockIdx.z;
    const int n = blockIdx.x * 128 + threadIdx.x;
    const int m0 = blockIdx.y * 256;
    const int mstart = max(m0, n), mend = m0 + 256;
    if (mstart >= mend) return;
    const __half* Fb = F + (long long)b * SS * SS;
    float s = 0.f;
    for (int m = mstart; m < mend; m++) s += __half2float(Fb[(long long)m * SS + n]);
    atomicAdd(&denom[b * SS + n], s);
}

// vpsT[b][d][k] = half(vp/denom * 4096)^T ; colv[b][d] += col sums (f32, unscaled)
__global__ void scale_transpose(const float* __restrict__ vp, const float* __restrict__ denom,
                                __half* __restrict__ vpsT, float* __restrict__ colv) {
    __shared__ float t[32][33];
    __shared__ float cp_[32];
    const int b = blockIdx.z;
    const float* vpb = vp + (long long)b * SS * DD;
    __half* vtb = vpsT + (long long)b * DD * SS;
    const int d0 = blockIdx.x * 32, k0 = blockIdx.y * 32;
    const int tx = threadIdx.x, ty = threadIdx.y;
    if (ty == 0) cp_[tx] = 0.f;
    __syncthreads();
    float local = 0.f;
    for (int i = ty; i < 32; i += 8) {
        const int kk = k0 + i;
        const float val = vpb[(long long)kk * DD + d0 + tx] * (1.0f / denom[b * SS + kk]);
        t[i][tx] = val;
        local += val;
    }
    atomicAdd(&cp_[tx], local);
    __syncthreads();
    for (int i = ty; i < 32; i += 8)
        vtb[(long long)(d0 + i) * SS + k0 + tx] = __float2half(t[tx][i] * VPS_SC);
    if (ty == 0) atomicAdd(&colv[b * DD + d0 + tx], cp_[tx]);
}

// pre-init d_out rows 1024..2047 with colv (split-K tiles RED into these rows)
__global__ void init_out(float* __restrict__ out, const float* __restrict__ colv) {
    const int i = blockIdx.x * 256 + threadIdx.x;  // 0..524287 float4
    const int row = i >> 7;                // 0..4095
    const int z = row >> 10;
    const int m = 1024 + (row & 1023);
    const int n = (i & 127) << 2;
    const float4 c = *(const float4*)(colv + z * DD + n);
    *(float4*)(out + ((long long)z * SS + m) * DD + n) = c;
}

// ---------------- launch ----------------
extern "C" void kernel_launch(void* const* d_in, const int* in_sizes, int n_in,
                              void* d_out, int out_size) {
    (void)in_sizes; (void)n_in; (void)out_size;
    const float* q   = (const float*)d_in[0];
    const float* k   = (const float*)d_in[1];
    const float* v   = (const float*)d_in[2];
    const float* WQw = (const float*)d_in[3];
    const float* WQb = (const float*)d_in[4];
    const float* WKw = (const float*)d_in[5];
    const float* WKb = (const float*)d_in[6];
    const float* WVw = (const float*)d_in[7];
    const float* WVb = (const float*)d_in[8];

    void *xq, *xk, *xv, *Wq, *Wk, *Wv, *qp, *kp, *vp, *F, *vpsT, *denom, *colv;
    cudaGetSymbolAddress(&xq, g_xq);
    cudaGetSymbolAddress(&xk, g_xk);
    cudaGetSymbolAddress(&xv, g_xv);
    cudaGetSymbolAddress(&Wq, g_Wq);
    cudaGetSymbolAddress(&Wk, g_Wk);
    cudaGetSymbolAddress(&Wv, g_Wv);
    cudaGetSymbolAddress(&qp, g_qp);
    cudaGetSymbolAddress(&kp, g_kp);
    cudaGetSymbolAddress(&vp, g_vp);
    cudaGetSymbolAddress(&F, g_F);
    cudaGetSymbolAddress(&vpsT, g_vpsT);
    cudaGetSymbolAddress(&denom, g_denom);
    cudaGetSymbolAddress(&colv, g_colv);

    // one-time stream/event infra (no device memory; created outside graph capture)
    static cudaStream_t sB = nullptr;
    static cudaEvent_t evX = nullptr, evV = nullptr;
    if (!sB) {
        cudaStreamCreateWithFlags(&sB, cudaStreamNonBlocking);
        cudaEventCreateWithFlags(&evX, cudaEventDisableTiming);
        cudaEventCreateWithFlags(&evV, cudaEventDisableTiming);
    }

    const int nx = BB * SS * DD;
    const int nw = DD * DD;

    // stream 0: cvts + init
    {
        CvtP pb; pb.s[0] = (const float4*)q; pb.s[1] = (const float4*)k; pb.s[2] = (const float4*)v;
        pb.d[0] = (__nv_bfloat162*)xq; pb.d[1] = (__nv_bfloat162*)xk; pb.d[2] = (__nv_bfloat162*)xv;
        pb.n4 = nx / 4;
        cvt_multi<<<dim3(nx / 4 / 256, 3), 256>>>(pb);
        CvtP pw; pw.s[0] = (const float4*)WQw; pw.s[1] = (const float4*)WKw; pw.s[2] = (const float4*)WVw;
        pw.d[0] = (__nv_bfloat162*)Wq; pw.d[1] = (__nv_bfloat162*)Wk; pw.d[2] = (__nv_bfloat162*)Wv;
        pw.n4 = nw / 4;
        cvt_multi<<<dim3(nw / 4 / 256, 3), 256>>>(pw);
    }
    init_dc<<<(BB * SS + 255) / 256, 256>>>((float*)denom, (float*)colv);
    cudaEventRecord(evX, 0);

    // stream B: vp projection (z=2), concurrent with proj-qk + QK on stream 0
    {
        cudaStreamWaitEvent(sB, evX, 0);
        GP p{};
        p.A0 = xq; p.A1 = xk; p.A2 = xv;
        p.B0 = Wq; p.B1 = Wk; p.B2 = Wv;
        p.C0 = qp; p.C1 = kp; p.C2 = vp;
        p.aux0 = WQb; p.aux1 = WKb; p.aux2 = WVb;
        p.K = DD; p.ldc = DD; p.zbase = 2;
        gemm_proj<<<dim3(DD / BN, BB * SS / BM, 1), 256, 0, sB>>>(p);
        cudaEventRecord(evV, sB);
    }

    // stream 0: qp/kp projections (z=0,1)
    {
        GP p{};
        p.A0 = xq; p.A1 = xk; p.A2 = xv;
        p.B0 = Wq; p.B1 = Wk; p.B2 = Wv;
        p.C0 = qp; p.C1 = kp; p.C2 = vp;
        p.aux0 = WQb; p.aux1 = WKb; p.aux2 = WVb;
        p.K = DD; p.ldc = DD; p.zbase = 0;
        gemm_proj<<<dim3(DD / BN, BB * SS / BM, 2), 256>>>(p);
    }

    // F[b][q][k] = (q>=k) ? expm1(scale*qk) : 0  (f16 acc) — triangle tiles
    {
        GP p{};
        p.A0 = qp; p.B0 = kp; p.C0 = F;
        p.sA = (long long)SS * DD; p.sB = (long long)SS * DD; p.sCb = (long long)SS * SS * 2;
        p.K = DD; p.ldc = SS;
        const int NT = SS / BM;
        const int ntri = NT * (NT + 1) / 2;  // 136
        gemm_h<EPI_QK><<<dim3(ntri, 1, BB), 256>>>(p);
    }

    colsum_F<<<dim3(SS / 128, 8, BB), 128>>>((const __half*)F, (float*)denom);

    // join: scale_transpose needs vp (stream B) + denom (stream 0)
    cudaStreamWaitEvent(0, evV, 0);
    scale_transpose<<<dim3(DD / 32, SS / 32, BB), dim3(32, 8)>>>(
        (const float*)vp, (const float*)denom, (__half*)vpsT, (float*)colv);

    // pre-init rows 1024..2047 of d_out with colv (RED targets)
    init_out<<<524288 / 256, 256>>>((float*)d_out, (const float*)colv);

    // out = (F . vpsT) * 1/4096 + colv  (f16 acc, split-K schedule: 384 CTAs)
    {
        GP p{};
        p.A0 = F; p.B0 = vpsT; p.C0 = d_out;
        p.aux0 = (const float*)colv; p.auxStride = DD;
        p.sA = (long long)SS * SS; p.sB = (long long)DD * SS; p.sCb = (long long)SS * DD * 4;
        p.K = SS; p.ldc = DD;
        gemm_h<EPI_OUT><<<dim3(384, 1, 1), 256>>>(p);
    }
}

// round 15
// speedup vs baseline: 1.1206x; 1.0206x over previous
#include <cuda_runtime.h>
#include <cuda_bf16.h>
#include <cuda_fp16.h>
#include <cstdint>
#include <math.h>

#define BB 4
#define SS 2048
#define DD 512
#define SCALE_F 0.04419417382415922f  // 1/sqrt(512)

#define BM 128
#define BN 128
#define BK 32
#define PAD 40
#define VPS_SC 4096.0f
#define VPS_DEQ (1.0f / 4096.0f)

// ---------------- scratch ----------------
static __device__ __nv_bfloat16 g_xq[BB * SS * DD];
static __device__ __nv_bfloat16 g_xk[BB * SS * DD];
static __device__ __nv_bfloat16 g_xv[BB * SS * DD];
static __device__ __nv_bfloat16 g_Wq[DD * DD];
static __device__ __nv_bfloat16 g_Wk[DD * DD];
static __device__ __nv_bfloat16 g_Wv[DD * DD];
static __device__ __half        g_qp[BB * SS * DD];
static __device__ __half        g_kp[BB * SS * DD];
static __device__ float         g_vp[BB * SS * DD];
// F: masked (upper) region never written, never read (zero-init device global)
static __device__ __half        g_F[(size_t)BB * SS * SS];
static __device__ __half        g_vpsT[BB * DD * SS];  // (vp/denom)^T * 4096
static __device__ float         g_denom[BB * SS];
static __device__ float         g_colv[BB * DD];

// ---------------- PTX helpers ----------------
__device__ __forceinline__ uint32_t s_u32(const void* p) {
    return (uint32_t)__cvta_generic_to_shared(p);
}
__device__ __forceinline__ void cp16(uint32_t d, const void* s) {
    asm volatile("cp.async.cg.shared.global [%0], [%1], 16;" :: "r"(d), "l"(s));
}
__device__ __forceinline__ void cpcommit() { asm volatile("cp.async.commit_group;"); }
template <int N>
__device__ __forceinline__ void cpwait() {
    asm volatile("cp.async.wait_group %0;" :: "n"(N));
}
__device__ __forceinline__ void ldm4(uint32_t* r, uint32_t a) {
    asm volatile("ldmatrix.sync.aligned.m8n8.x4.shared.b16 {%0,%1,%2,%3}, [%4];"
                 : "=r"(r[0]), "=r"(r[1]), "=r"(r[2]), "=r"(r[3]) : "r"(a));
}
__device__ __forceinline__ void mma16816(float* d, const uint32_t* a, uint32_t b0, uint32_t b1) {
    asm volatile(
        "mma.sync.aligned.m16n8k16.row.col.f32.bf16.bf16.f32 "
        "{%0,%1,%2,%3}, {%4,%5,%6,%7}, {%8,%9}, {%0,%1,%2,%3};"
        : "+f"(d[0]), "+f"(d[1]), "+f"(d[2]), "+f"(d[3])
        : "r"(a[0]), "r"(a[1]), "r"(a[2]), "r"(a[3]), "r"(b0), "r"(b1));
}
__device__ __forceinline__ void mma16816h(uint32_t* d, const uint32_t* a, uint32_t b0, uint32_t b1) {
    asm volatile(
        "mma.sync.aligned.m16n8k16.row.col.f16.f16.f16.f16 "
        "{%0,%1}, {%2,%3,%4,%5}, {%6,%7}, {%0,%1};"
        : "+r"(d[0]), "+r"(d[1])
        : "r"(a[0]), "r"(a[1]), "r"(a[2]), "r"(a[3]), "r"(b0), "r"(b1));
}
__device__ __forceinline__ float expm1_poly(float s) {
    return s * fmaf(s, fmaf(s, fmaf(s, 0.041666667f, 0.16666667f), 0.5f), 1.0f);
}

// ---------------- params ----------------
struct GP {
    const void *A0, *A1, *A2, *B0, *B1, *B2;
    void *C0, *C1, *C2;
    const float *aux0, *aux1, *aux2;
    long long sA, sB, sCb;
    int K, ldc, auxStride;
    int zbase;
    float* denom;
};

// ================= proj GEMM: bf16 in, f32 acc (2 CTAs/SM) =================
// z=0,1 -> half out (qp,kp); z=2 -> f32 out (vp)
__global__ __launch_bounds__(256, 2) void gemm_proj(GP p) {
    __shared__ __align__(16) __nv_bfloat16 As[2][BM][PAD];
    __shared__ __align__(16) __nv_bfloat16 Bs[2][BM][PAD];

    const int tid = threadIdx.x;
    const int warp = tid >> 5, lane = tid & 31;
    const int z = blockIdx.z + p.zbase;
    const int m0 = blockIdx.y * BM, n0 = blockIdx.x * BN;

    const __nv_bfloat16* Ag = (const __nv_bfloat16*)(z == 0 ? p.A0 : (z == 1 ? p.A1 : p.A2));
    const __nv_bfloat16* Bg = (const __nv_bfloat16*)(z == 0 ? p.B0 : (z == 1 ? p.B1 : p.B2));
    char* Cg = (char*)(z == 0 ? p.C0 : (z == 1 ? p.C1 : p.C2));
    const float* aux = z == 0 ? p.aux0 : (z == 1 ? p.aux1 : p.aux2);

    const int K = p.K;
    const int KT = K >> 5;
    const int wm = (warp & 3) * 32, wn = (warp >> 2) * 64;
    const int lrow = tid >> 2, lcol = (tid & 3) << 3;

    auto issue = [&](int buf, int kt) {
        const int k0 = kt * BK;
        cp16(s_u32(&As[buf][lrow][lcol]),      Ag + (long long)(m0 + lrow) * K + k0 + lcol);
        cp16(s_u32(&As[buf][lrow + 64][lcol]), Ag + (long long)(m0 + lrow + 64) * K + k0 + lcol);
        cp16(s_u32(&Bs[buf][lrow][lcol]),      Bg + (long long)(n0 + lrow) * K + k0 + lcol);
        cp16(s_u32(&Bs[buf][lrow + 64][lcol]), Bg + (long long)(n0 + lrow + 64) * K + k0 + lcol);
        cpcommit();
    };

    float acc[2][8][4];
#pragma unroll
    for (int i = 0; i < 2; i++)
#pragma unroll
        for (int j = 0; j < 8; j++)
#pragma unroll
            for (int c = 0; c < 4; c++) acc[i][j][c] = 0.f;

    issue(0, 0);

    const int mi = lane >> 3, r8 = lane & 7;
    const int roff = ((mi & 1) << 3) + r8;
    const int koff0 = (mi >> 1) << 3;

    for (int kt = 0; kt < KT; kt++) {
        if (kt + 1 < KT) { issue((kt + 1) & 1, kt + 1); cpwait<1>(); }
        else             { cpwait<0>(); }
        __syncthreads();
        const int buf = kt & 1;
#pragma unroll
        for (int ks = 0; ks < BK; ks += 16) {
            uint32_t af[2][4], bf[4][4];
#pragma unroll
            for (int im = 0; im < 2; im++)
                ldm4(af[im], s_u32(&As[buf][wm + im * 16 + roff][ks + koff0]));
#pragma unroll
            for (int jb = 0; jb < 4; jb++)
                ldm4(bf[jb], s_u32(&Bs[buf][wn + jb * 16 + roff][ks + koff0]));
#pragma unroll
            for (int im = 0; im < 2; im++)
#pragma unroll
                for (int jn = 0; jn < 8; jn++)
                    mma16816(acc[im][jn], af[im], bf[jn >> 1][jn & 1], bf[jn >> 1][2 + (jn & 1)]);
        }
        __syncthreads();
    }

    const int er = lane >> 2, ec = (lane & 3) << 1;
#pragma unroll
    for (int im = 0; im < 2; im++) {
#pragma unroll
        for (int jn = 0; jn < 8; jn++) {
            const int m = m0 + wm + im * 16 + er;
            const int n = n0 + wn + jn * 8 + ec;
            const float ba = aux[n], bb2 = aux[n + 1];
            const float v0 = acc[im][jn][0] + ba, v1 = acc[im][jn][1] + bb2;
            const float v2 = acc[im][jn][2] + ba, v3 = acc[im][jn][3] + bb2;
            if (z == 2) {
                float* Cf = (float*)Cg;
                float2 lo; lo.x = v0; lo.y = v1;
                float2 hi; hi.x = v2; hi.y = v3;
                *(float2*)(Cf + (long long)m * p.ldc + n) = lo;
                *(float2*)(Cf + (long long)(m + 8) * p.ldc + n) = hi;
            } else {
                __half* Ch = (__half*)Cg;
                *(__half2*)(Ch + (long long)m * p.ldc + n) = __floats2half2_rn(v0, v1);
                *(__half2*)(Ch + (long long)(m + 8) * p.ldc + n) = __floats2half2_rn(v2, v3);
            }
        }
    }
}

// ================= f16-acc GEMM (QK, OUT) — 2 CTAs/SM =================
enum { EPI_QK = 0, EPI_OUT = 1 };

template <int EPI>
__global__ __launch_bounds__(256, 2) void gemm_h(GP p) {
    __shared__ __align__(16) __half As[2][BM][PAD];
    __shared__ __align__(16) __half Bs[2][BM][PAD];
    __shared__ float colacc[BN];  // QK only

    const int tid = threadIdx.x;
    const int warp = tid >> 5, lane = tid & 31;

    int m0, n0, z, kbeg, kfin, lev = 0;
    if (EPI == EPI_QK) {
        z = blockIdx.z;
        const int t = blockIdx.x;  // lower-triangle enumeration
        int m_t = (int)floorf((sqrtf(8.0f * (float)t + 1.0f) - 1.0f) * 0.5f);
        while ((m_t + 1) * (m_t + 2) / 2 <= t) m_t++;
        while (m_t * (m_t + 1) / 2 > t) m_t--;
        const int n_t = t - m_t * (m_t + 1) / 2;
        m0 = m_t * BM; n0 = n_t * BN;
        kbeg = 0; kfin = p.K;
        if (tid < BN) colacc[tid] = 0.f;  // ordered before epilogue use by mainloop syncs
    } else {
        // split-K schedule: 24 groups of 16 CTAs, ordered by chunk K desc.
        // levels 9..16 split at lev*64 (BK multiple); levels 1..8 unsplit.
        static const signed char LEVT[24] = {16,16, 8,15,15,14,14, 7,13,13,12,12,
                                              6,11,11,10,10, 5, 9, 9, 4, 3, 2, 1};
        static const signed char CHT[24]  = { 0, 1,-1, 0, 1, 0, 1,-1, 0, 1, 0, 1,
                                             -1, 0, 1, 0, 1,-1, 0, 1,-1,-1,-1,-1};
        const int g = blockIdx.x >> 4, idx = blockIdx.x & 15;
        lev = LEVT[g];
        const int ch = CHT[g];
        m0 = (lev - 1) * BM;
        z = idx >> 2;
        n0 = (idx & 3) * BN;
        if (ch < 0) { kbeg = 0; kfin = lev * BM; lev = 0; }  // lev=0 marks plain-store path
        else {
            const int half = lev * 64;  // multiple of 32
            kbeg = ch ? half : 0;
            kfin = ch ? lev * BM : half;
            lev = ch ? 1 : 2;           // 1 = RED partial, 2 = RED partial + colv
        }
    }

    const __half* Ag = (const __half*)p.A0 + (long long)z * p.sA;
    const __half* Bg = (const __half*)p.B0 + (long long)z * p.sB;
    char* Cg = (char*)p.C0 + (long long)z * p.sCb;
    const float* aux = p.aux0 ? (p.aux0 + (long long)z * p.auxStride) : nullptr;

    const int K = p.K;
    const int KTb = kbeg >> 5, KTe = kfin >> 5;
    const int wm = (warp & 3) * 32, wn = (warp >> 2) * 64;
    const int lrow = tid >> 2, lcol = (tid & 3) << 3;

    auto issue = [&](int buf, int kt) {
        const int k0 = kt * BK;
        cp16(s_u32(&As[buf][lrow][lcol]),      Ag + (long long)(m0 + lrow) * K + k0 + lcol);
        cp16(s_u32(&As[buf][lrow + 64][lcol]), Ag + (long long)(m0 + lrow + 64) * K + k0 + lcol);
        cp16(s_u32(&Bs[buf][lrow][lcol]),      Bg + (long long)(n0 + lrow) * K + k0 + lcol);
        cp16(s_u32(&Bs[buf][lrow + 64][lcol]), Bg + (long long)(n0 + lrow + 64) * K + k0 + lcol);
        cpcommit();
    };

    uint32_t acc[2][8][2];
#pragma unroll
    for (int i = 0; i < 2; i++)
#pragma unroll
        for (int j = 0; j < 8; j++) { acc[i][j][0] = 0u; acc[i][j][1] = 0u; }

    issue(KTb & 1, KTb);

    const int mi = lane >> 3, r8 = lane & 7;
    const int roff = ((mi & 1) << 3) + r8;
    const int koff0 = (mi >> 1) << 3;

    for (int kt = KTb; kt < KTe; kt++) {
        if (kt + 1 < KTe) { issue((kt + 1) & 1, kt + 1); cpwait<1>(); }
        else              { cpwait<0>(); }
        __syncthreads();
        const int buf = kt & 1;
#pragma unroll
        for (int ks = 0; ks < BK; ks += 16) {
            uint32_t af[2][4], bf[4][4];
#pragma unroll
            for (int im = 0; im < 2; im++)
                ldm4(af[im], s_u32(&As[buf][wm + im * 16 + roff][ks + koff0]));
#pragma unroll
            for (int jb = 0; jb < 4; jb++)
                ldm4(bf[jb], s_u32(&Bs[buf][wn + jb * 16 + roff][ks + koff0]));
#pragma unroll
            for (int im = 0; im < 2; im++)
#pragma unroll
                for (int jn = 0; jn < 8; jn++)
                    mma16816h(acc[im][jn], af[im], bf[jn >> 1][jn & 1], bf[jn >> 1][2 + (jn & 1)]);
        }
        __syncthreads();
    }

    const int er = lane >> 2, ec = (lane & 3) << 1;
    float cs0[8], cs1[8];
    if (EPI == EPI_QK) {
#pragma unroll
        for (int j = 0; j < 8; j++) { cs0[j] = 0.f; cs1[j] = 0.f; }
    }
#pragma unroll
    for (int im = 0; im < 2; im++) {
#pragma unroll
        for (int jn = 0; jn < 8; jn++) {
            const int m = m0 + wm + im * 16 + er;
            const int n = n0 + wn + jn * 8 + ec;
            const float2 lo2 = __half22float2(*(__half2*)&acc[im][jn][0]);
            const float2 hi2 = __half22float2(*(__half2*)&acc[im][jn][1]);
            if (EPI == EPI_QK) {
                float v0 = (m     >= n    ) ? expm1_poly(lo2.x * SCALE_F) : 0.f;
                float v1 = (m     >= n + 1) ? expm1_poly(lo2.y * SCALE_F) : 0.f;
                float v2 = (m + 8 >= n    ) ? expm1_poly(hi2.x * SCALE_F) : 0.f;
                float v3 = (m + 8 >= n + 1) ? expm1_poly(hi2.y * SCALE_F) : 0.f;
                cs0[jn] += v0 + v2;
                cs1[jn] += v1 + v3;
                __half* Ch = (__half*)Cg;
                *(__half2*)(Ch + (long long)m * p.ldc + n) = __floats2half2_rn(v0, v1);
                *(__half2*)(Ch + (long long)(m + 8) * p.ldc + n) = __floats2half2_rn(v2, v3);
            } else {
                float* Cf = (float*)Cg;
                if (lev) {
                    // split tiles: rows >= 1024 pre-zeroed; RED-accumulate.
                    // lev==2 (first chunk) folds colv in exactly once.
                    const float ba = (lev == 2) ? aux[n] : 0.f;
                    const float bb2 = (lev == 2) ? aux[n + 1] : 0.f;
                    atomicAdd(Cf + (long long)m * p.ldc + n,           lo2.x * VPS_DEQ + ba);
                    atomicAdd(Cf + (long long)m * p.ldc + n + 1,       lo2.y * VPS_DEQ + bb2);
                    atomicAdd(Cf + (long long)(m + 8) * p.ldc + n,     hi2.x * VPS_DEQ + ba);
                    atomicAdd(Cf + (long long)(m + 8) * p.ldc + n + 1, hi2.y * VPS_DEQ + bb2);
                } else {
                    const float ba = aux[n], bb2 = aux[n + 1];
                    float2 lo; lo.x = lo2.x * VPS_DEQ + ba; lo.y = lo2.y * VPS_DEQ + bb2;
                    float2 hi; hi.x = hi2.x * VPS_DEQ + ba; hi.y = hi2.y * VPS_DEQ + bb2;
                    *(float2*)(Cf + (long long)m * p.ldc + n) = lo;
                    *(float2*)(Cf + (long long)(m + 8) * p.ldc + n) = hi;
                }
            }
        }
    }
    if (EPI == EPI_QK) {
        // fused column sums -> denom (replaces the colsum_F pass)
#pragma unroll
        for (int jn = 0; jn < 8; jn++) {
            atomicAdd(&colacc[wn + jn * 8 + ec], cs0[jn]);
            atomicAdd(&colacc[wn + jn * 8 + ec + 1], cs1[jn]);
        }
        __syncthreads();
        if (tid < BN) atomicAdd(&p.denom[z * SS + n0 + tid], colacc[tid]);
    }
}

// ---------------- aux kernels ----------------
struct CvtP { const float4* s[3]; __nv_bfloat162* d[3]; int n4; };
__global__ void cvt_multi(CvtP p) {
    const int t = blockIdx.y;
    const int i = blockIdx.x * 256 + threadIdx.x;
    if (i < p.n4) {
        const float4 x = p.s[t][i];
        p.d[t][2 * i]     = __floats2bfloat162_rn(x.x, x.y);
        p.d[t][2 * i + 1] = __floats2bfloat162_rn(x.z, x.w);
    }
}

__global__ void init_dc(float* __restrict__ denom, float* __restrict__ colv) {
    const int i = blockIdx.x * blockDim.x + threadIdx.x;
    if (i < BB * SS) denom[i] = (float)SS;
    if (i < BB * DD) colv[i] = 0.f;
}

// zero d_out rows 1024..2047 (RED targets for split-K OUT tiles)
__global__ void zero_out(float* __restrict__ out) {
    const int i = blockIdx.x * 256 + threadIdx.x;  // 0..524287 float4
    const int row = i >> 7;                        // 0..4095
    const int z = row >> 10;
    const int m = 1024 + (row & 1023);
    const int n = (i & 127) << 2;
    *(float4*)(out + ((long long)z * SS + m) * DD + n) = make_float4(0.f, 0.f, 0.f, 0.f);
}

// vpsT[b][d][k] = half(vp/denom * 4096)^T ; colv[b][d] += col sums (f32, unscaled)
__global__ void scale_transpose(const float* __restrict__ vp, const float* __restrict__ denom,
                                __half* __restrict__ vpsT, float* __restrict__ colv) {
    __shared__ float t[32][33];
    __shared__ float cp_[32];
    const int b = blockIdx.z;
    const float* vpb = vp + (long long)b * SS * DD;
    __half* vtb = vpsT + (long long)b * DD * SS;
    const int d0 = blockIdx.x * 32, k0 = blockIdx.y * 32;
    const int tx = threadIdx.x, ty = threadIdx.y;
    if (ty == 0) cp_[tx] = 0.f;
    __syncthreads();
    float local = 0.f;
    for (int i = ty; i < 32; i += 8) {
        const int kk = k0 + i;
        const float val = vpb[(long long)kk * DD + d0 + tx] * (1.0f / denom[b * SS + kk]);
        t[i][tx] = val;
        local += val;
    }
    atomicAdd(&cp_[tx], local);
    __syncthreads();
    for (int i = ty; i < 32; i += 8)
        vtb[(long long)(d0 + i) * SS + k0 + tx] = __float2half(t[tx][i] * VPS_SC);
    if (ty == 0) atomicAdd(&colv[b * DD + d0 + tx], cp_[tx]);
}

// ---------------- launch ----------------
extern "C" void kernel_launch(void* const* d_in, const int* in_sizes, int n_in,
                              void* d_out, int out_size) {
    (void)in_sizes; (void)n_in; (void)out_size;
    const float* q   = (const float*)d_in[0];
    const float* k   = (const float*)d_in[1];
    const float* v   = (const float*)d_in[2];
    const float* WQw = (const float*)d_in[3];
    const float* WQb = (const float*)d_in[4];
    const float* WKw = (const float*)d_in[5];
    const float* WKb = (const float*)d_in[6];
    const float* WVw = (const float*)d_in[7];
    const float* WVb = (const float*)d_in[8];

    void *xq, *xk, *xv, *Wq, *Wk, *Wv, *qp, *kp, *vp, *F, *vpsT, *denom, *colv;
    cudaGetSymbolAddress(&xq, g_xq);
    cudaGetSymbolAddress(&xk, g_xk);
    cudaGetSymbolAddress(&xv, g_xv);
    cudaGetSymbolAddress(&Wq, g_Wq);
    cudaGetSymbolAddress(&Wk, g_Wk);
    cudaGetSymbolAddress(&Wv, g_Wv);
    cudaGetSymbolAddress(&qp, g_qp);
    cudaGetSymbolAddress(&kp, g_kp);
    cudaGetSymbolAddress(&vp, g_vp);
    cudaGetSymbolAddress(&F, g_F);
    cudaGetSymbolAddress(&vpsT, g_vpsT);
    cudaGetSymbolAddress(&denom, g_denom);
    cudaGetSymbolAddress(&colv, g_colv);

    // one-time stream/event infra (no device memory; created outside graph capture)
    static cudaStream_t sB = nullptr;
    static cudaEvent_t evR = nullptr, evX = nullptr, evV = nullptr, evZ = nullptr;
    if (!sB) {
        cudaStreamCreateWithFlags(&sB, cudaStreamNonBlocking);
        cudaEventCreateWithFlags(&evR, cudaEventDisableTiming);
        cudaEventCreateWithFlags(&evX, cudaEventDisableTiming);
        cudaEventCreateWithFlags(&evV, cudaEventDisableTiming);
        cudaEventCreateWithFlags(&evZ, cudaEventDisableTiming);
    }

    const int nx = BB * SS * DD;
    const int nw = DD * DD;

    // root fork: sB must enter capture via a wait on an event recorded
    // in the capturing stream BEFORE any work is launched on it.
    cudaEventRecord(evR, 0);
    cudaStreamWaitEvent(sB, evR, 0);

    // stream B: zero split-K RED targets (no data dependencies)
    zero_out<<<524288 / 256, 256, 0, sB>>>((float*)d_out);
    cudaEventRecord(evZ, sB);

    // stream 0: cvts + init
    {
        CvtP pb; pb.s[0] = (const float4*)q; pb.s[1] = (const float4*)k; pb.s[2] = (const float4*)v;
        pb.d[0] = (__nv_bfloat162*)xq; pb.d[1] = (__nv_bfloat162*)xk; pb.d[2] = (__nv_bfloat162*)xv;
        pb.n4 = nx / 4;
        cvt_multi<<<dim3(nx / 4 / 256, 3), 256>>>(pb);
        CvtP pw; pw.s[0] = (const float4*)WQw; pw.s[1] = (const float4*)WKw; pw.s[2] = (const float4*)WVw;
        pw.d[0] = (__nv_bfloat162*)Wq; pw.d[1] = (__nv_bfloat162*)Wk; pw.d[2] = (__nv_bfloat162*)Wv;
        pw.n4 = nw / 4;
        cvt_multi<<<dim3(nw / 4 / 256, 3), 256>>>(pw);
    }
    init_dc<<<(BB * SS + 255) / 256, 256>>>((float*)denom, (float*)colv);
    cudaEventRecord(evX, 0);

    // stream B: vp projection (z=2), concurrent with proj-qk + QK on stream 0
    {
        cudaStreamWaitEvent(sB, evX, 0);
        GP p{};
        p.A0 = xq; p.A1 = xk; p.A2 = xv;
        p.B0 = Wq; p.B1 = Wk; p.B2 = Wv;
        p.C0 = qp; p.C1 = kp; p.C2 = vp;
        p.aux0 = WQb; p.aux1 = WKb; p.aux2 = WVb;
        p.K = DD; p.ldc = DD; p.zbase = 2;
        gemm_proj<<<dim3(DD / BN, BB * SS / BM, 1), 256, 0, sB>>>(p);
        cudaEventRecord(evV, sB);
    }

    // stream 0: qp/kp projections (z=0,1)
    {
        GP p{};
        p.A0 = xq; p.A1 = xk; p.A2 = xv;
        p.B0 = Wq; p.B1 = Wk; p.B2 = Wv;
        p.C0 = qp; p.C1 = kp; p.C2 = vp;
        p.aux0 = WQb; p.aux1 = WKb; p.aux2 = WVb;
        p.K = DD; p.ldc = DD; p.zbase = 0;
        gemm_proj<<<dim3(DD / BN, BB * SS / BM, 2), 256>>>(p);
    }

    // F[b][q][k] = (q>=k) ? expm1(scale*qk) : 0  (f16 acc) — triangle tiles,
    // fused column sums -> denom (init_dc pre-seeded denom with S)
    {
        GP p{};
        p.A0 = qp; p.B0 = kp; p.C0 = F;
        p.sA = (long long)SS * DD; p.sB = (long long)SS * DD; p.sCb = (long long)SS * SS * 2;
        p.K = DD; p.ldc = SS;
        p.denom = (float*)denom;
        const int NT = SS / BM;
        const int ntri = NT * (NT + 1) / 2;  // 136
        gemm_h<EPI_QK><<<dim3(ntri, 1, BB), 256>>>(p);
    }

    // join: scale_transpose needs vp (stream B) + denom (stream 0, complete after QK)
    cudaStreamWaitEvent(0, evV, 0);
    scale_transpose<<<dim3(DD / 32, SS / 32, BB), dim3(32, 8)>>>(
        (const float*)vp, (const float*)denom, (__half*)vpsT, (float*)colv);

    // out = (F . vpsT) * 1/4096 + colv  (f16 acc, split-K schedule: 384 CTAs)
    cudaStreamWaitEvent(0, evZ, 0);
    {
        GP p{};
        p.A0 = F; p.B0 = vpsT; p.C0 = d_out;
        p.aux0 = (const float*)colv; p.auxStride = DD;
        p.sA = (long long)SS * SS; p.sB = (long long)DD * SS; p.sCb = (long long)SS * DD * 4;
        p.K = SS; p.ldc = DD;
        gemm_h<EPI_OUT><<<dim3(384, 1, 1), 256>>>(p);
    }
}